// round 7
// baseline (speedup 1.0000x reference)
#include <cuda_runtime.h>
#include <cuda_bf16.h>

constexpr int Bb = 16, Ss = 64, Nn = 2048, Ee = 256;
constexpr int KSPLIT = 16;

typedef unsigned long long ull;

__device__ __forceinline__ void fma2(ull& d, ull a, ull b) {
    asm("fma.rn.f32x2 %0, %1, %2, %0;" : "+l"(d) : "l"(a), "l"(b));
}
__device__ __forceinline__ float2 u2f(ull v) {
    float2 f; asm("mov.b64 {%0, %1}, %2;" : "=f"(f.x), "=f"(f.y) : "l"(v)); return f;
}

__device__ float g_Q[Bb * Nn * Ee];
__device__ float g_K[Bb * Nn * Ee];
__device__ float g_E[(size_t)Bb * Nn * Nn];
__device__ float g_cs[Bb * Nn];
__device__ float g_xn[Bb * Ss * Nn];
__device__ float g_AGG[Ss * Bb * Nn];
__device__ float g_part[3 * KSPLIT * Bb * Nn];
__device__ float g_h[Bb * Nn];

// ---------------- K0: zero cs, h, AGG ----------------
__global__ void k0_zero() {
    int idx = blockIdx.x * 256 + threadIdx.x;
    if (idx < Bb * Nn) { g_cs[idx] = 0.f; g_h[idx] = 0.f; }
    if (idx < Ss * Bb * Nn) g_AGG[idx] = 0.f;
}

// ---------------- K1: Q,K projection (small; plain FFMA) -----------------
__global__ __launch_bounds__(256) void k1_qk(
    const float* __restrict__ x,
    const float* __restrict__ Wq, const float* __restrict__ bq,
    const float* __restrict__ Wk, const float* __restrict__ bk)
{
    __shared__ float As[16][132];
    __shared__ float wqs[64][16];
    __shared__ float wks[64][16];
    int tid = threadIdx.x;
    int b = blockIdx.z, nbase = blockIdx.x * 128, ebase = blockIdx.y * 64;
    int tn = tid % 16, te = tid / 16;

    float4 accq[8], acck[8];
    #pragma unroll
    for (int i = 0; i < 8; ++i) { accq[i] = make_float4(0,0,0,0); acck[i] = make_float4(0,0,0,0); }

    for (int kc = 0; kc < 4; ++kc) {
        int kbase = kc * 16;
        #pragma unroll
        for (int p = 0; p < 2; ++p) {
            int v = tid + 256 * p;
            int k = v / 32, mq = v % 32;
            *(float4*)&As[k][mq * 4] =
                *(const float4*)&x[((size_t)(b * Ss + kbase + k)) * Nn + nbase + mq * 4];
        }
        {
            int e = tid / 4, kq = tid % 4;
            *(float4*)&wqs[e][kq * 4] = *(const float4*)&Wq[(ebase + e) * Ss + kbase + kq * 4];
            *(float4*)&wks[e][kq * 4] = *(const float4*)&Wk[(ebase + e) * Ss + kbase + kq * 4];
        }
        __syncthreads();
        #pragma unroll
        for (int kk = 0; kk < 16; ++kk) {
            float4 alo = *(float4*)&As[kk][tn * 8];
            float4 ahi = *(float4*)&As[kk][tn * 8 + 4];
            float av[8] = {alo.x, alo.y, alo.z, alo.w, ahi.x, ahi.y, ahi.z, ahi.w};
            float wq0 = wqs[te*4+0][kk], wq1 = wqs[te*4+1][kk];
            float wq2 = wqs[te*4+2][kk], wq3 = wqs[te*4+3][kk];
            float wk0 = wks[te*4+0][kk], wk1 = wks[te*4+1][kk];
            float wk2 = wks[te*4+2][kk], wk3 = wks[te*4+3][kk];
            #pragma unroll
            for (int i = 0; i < 8; ++i) {
                accq[i].x += av[i]*wq0; accq[i].y += av[i]*wq1;
                accq[i].z += av[i]*wq2; accq[i].w += av[i]*wq3;
                acck[i].x += av[i]*wk0; acck[i].y += av[i]*wk1;
                acck[i].z += av[i]*wk2; acck[i].w += av[i]*wk3;
            }
        }
        __syncthreads();
    }
    float4 bq4 = *(const float4*)&bq[ebase + te * 4];
    float4 bk4 = *(const float4*)&bk[ebase + te * 4];
    #pragma unroll
    for (int i = 0; i < 8; ++i) {
        int n = nbase + tn * 8 + i;
        size_t o = ((size_t)(b * Nn + n)) * Ee + ebase + te * 4;
        float4 q = accq[i]; q.x += bq4.x; q.y += bq4.y; q.z += bq4.z; q.w += bq4.w;
        float4 kk4 = acck[i]; kk4.x += bk4.x; kk4.y += bk4.y; kk4.z += bk4.z; kk4.w += bk4.w;
        *(float4*)&g_Q[o] = q;
        *(float4*)&g_K[o] = kk4;
    }
}

// ---------------- K2: scores + mask + exp + colsum (f32x2) ----------------
// E[b,i,j] = adj[i,j]>0 ? exp(Q[b,i,:].K[b,j,:]) : 0 ; cs[b,j] += col sum.
// Q rows duplicated {v,v} in smem so the inner loop is pure FFMA2, no packs.
__global__ __launch_bounds__(256) void k2_scores(const int* __restrict__ adj)
{
    __shared__ __align__(16) float2 As2[16][132];  // duplicated Q [k][i]
    __shared__ __align__(16) float  Bs [16][132];  // K [k][j]
    int tid = threadIdx.x;
    int b = blockIdx.z, mbase = blockIdx.y * 128, nbase = blockIdx.x * 128;
    int tx = tid % 16, ty = tid / 16;

    const float* Qb = g_Q + (size_t)b * Nn * Ee;
    const float* Kb = g_K + (size_t)b * Nn * Ee;

    ull acc[8][4];
    #pragma unroll
    for (int i = 0; i < 8; ++i)
        #pragma unroll
        for (int j = 0; j < 4; ++j) acc[i][j] = 0ull;

    for (int kc = 0; kc < 16; ++kc) {
        int kbase = kc * 16;
        #pragma unroll
        for (int p = 0; p < 2; ++p) {
            int v = tid + 256 * p;
            int m = v / 4, kq = v % 4;
            float4 a4 = *(const float4*)&Qb[(size_t)(mbase + m) * Ee + kbase + kq * 4];
            As2[kq*4+0][m] = make_float2(a4.x, a4.x);
            As2[kq*4+1][m] = make_float2(a4.y, a4.y);
            As2[kq*4+2][m] = make_float2(a4.z, a4.z);
            As2[kq*4+3][m] = make_float2(a4.w, a4.w);
            float4 b4 = *(const float4*)&Kb[(size_t)(nbase + m) * Ee + kbase + kq * 4];
            Bs[kq*4+0][m] = b4.x; Bs[kq*4+1][m] = b4.y; Bs[kq*4+2][m] = b4.z; Bs[kq*4+3][m] = b4.w;
        }
        __syncthreads();
        #pragma unroll
        for (int kk = 0; kk < 16; ++kk) {
            ulonglong2 a0 = *(ulonglong2*)&As2[kk][ty * 8 + 0];
            ulonglong2 a1 = *(ulonglong2*)&As2[kk][ty * 8 + 2];
            ulonglong2 a2 = *(ulonglong2*)&As2[kk][ty * 8 + 4];
            ulonglong2 a3 = *(ulonglong2*)&As2[kk][ty * 8 + 6];
            ulonglong2 b0 = *(ulonglong2*)&Bs[kk][tx * 8 + 0];
            ulonglong2 b1 = *(ulonglong2*)&Bs[kk][tx * 8 + 4];
            ull aa[8] = {a0.x, a0.y, a1.x, a1.y, a2.x, a2.y, a3.x, a3.y};
            ull bp[4] = {b0.x, b0.y, b1.x, b1.y};
            #pragma unroll
            for (int i = 0; i < 8; ++i) {
                fma2(acc[i][0], aa[i], bp[0]);
                fma2(acc[i][1], aa[i], bp[1]);
                fma2(acc[i][2], aa[i], bp[2]);
                fma2(acc[i][3], aa[i], bp[3]);
            }
        }
        __syncthreads();
    }

    float csum[8];
    #pragma unroll
    for (int j = 0; j < 8; ++j) csum[j] = 0.f;

    #pragma unroll
    for (int i = 0; i < 8; ++i) {
        int gi = mbase + ty * 8 + i;
        float cv[8];
        #pragma unroll
        for (int j2 = 0; j2 < 4; ++j2) {
            float2 t = u2f(acc[i][j2]);
            cv[2*j2] = t.x; cv[2*j2+1] = t.y;
        }
        const int* adjrow = adj + (size_t)gi * Nn + nbase + tx * 8;
        float* Erow = g_E + ((size_t)(b * Nn + gi)) * Nn + nbase + tx * 8;
        #pragma unroll
        for (int jv = 0; jv < 2; ++jv) {
            int4 a4 = *(const int4*)&adjrow[jv * 4];
            float4 e4;
            e4.x = (a4.x > 0) ? __expf(cv[jv*4+0]) : 0.f;
            e4.y = (a4.y > 0) ? __expf(cv[jv*4+1]) : 0.f;
            e4.z = (a4.z > 0) ? __expf(cv[jv*4+2]) : 0.f;
            e4.w = (a4.w > 0) ? __expf(cv[jv*4+3]) : 0.f;
            *(float4*)&Erow[jv * 4] = e4;
            csum[jv*4+0] += e4.x; csum[jv*4+1] += e4.y;
            csum[jv*4+2] += e4.z; csum[jv*4+3] += e4.w;
        }
    }
    #pragma unroll
    for (int j = 0; j < 8; ++j)
        atomicAdd(&g_cs[b * Nn + nbase + tx * 8 + j], csum[j]);
}

// ---------------- K3: xn = x / colsum ----------------
__global__ void k3_xn(const float* __restrict__ x) {
    int idx = blockIdx.x * 256 + threadIdx.x;
    if (idx < Bb * Ss * Nn) {
        int j = idx % Nn;
        int b = idx / (Ss * Nn);
        g_xn[idx] = x[idx] / g_cs[b * Nn + j];
    }
}

// ---------------- K4: AGG[t][b][i] = sum_j E[b,i,j]*xn[b,t,j] (f32x2) ----------------
__global__ __launch_bounds__(256) void k4_agg()
{
    __shared__ __align__(16) float2 es2[32][132];  // duplicated E [j][i]
    __shared__ __align__(16) float  xs [32][68];   // xn [j][t]
    int tid = threadIdx.x;
    int b = blockIdx.z, ibase = blockIdx.x * 128, jsp = blockIdx.y;
    int it = tid % 16, tt = tid / 16;

    const float* Eb = g_E + ((size_t)b * Nn + ibase) * Nn;
    const float* xb = g_xn + (size_t)b * Ss * Nn;

    ull acc[8][2];
    #pragma unroll
    for (int i = 0; i < 8; ++i) { acc[i][0] = 0ull; acc[i][1] = 0ull; }

    for (int jc = 0; jc < 32; ++jc) {
        int jbase = jsp * 1024 + jc * 32;
        #pragma unroll
        for (int p = 0; p < 4; ++p) {
            int v = tid + 256 * p;
            int i = v / 8, jq = v % 8;
            float4 e4 = *(const float4*)&Eb[(size_t)i * Nn + jbase + jq * 4];
            es2[jq*4+0][i] = make_float2(e4.x, e4.x);
            es2[jq*4+1][i] = make_float2(e4.y, e4.y);
            es2[jq*4+2][i] = make_float2(e4.z, e4.z);
            es2[jq*4+3][i] = make_float2(e4.w, e4.w);
        }
        #pragma unroll
        for (int p = 0; p < 2; ++p) {
            int v = tid + 256 * p;
            int t = v / 8, jq = v % 8;
            float4 x4 = *(const float4*)&xb[(size_t)t * Nn + jbase + jq * 4];
            xs[jq*4+0][t] = x4.x; xs[jq*4+1][t] = x4.y; xs[jq*4+2][t] = x4.z; xs[jq*4+3][t] = x4.w;
        }
        __syncthreads();
        #pragma unroll
        for (int jj = 0; jj < 32; ++jj) {
            ulonglong2 xv = *(ulonglong2*)&xs[jj][tt * 4];
            ulonglong2 e0 = *(ulonglong2*)&es2[jj][it * 8 + 0];
            ulonglong2 e1 = *(ulonglong2*)&es2[jj][it * 8 + 2];
            ulonglong2 e2 = *(ulonglong2*)&es2[jj][it * 8 + 4];
            ulonglong2 e3 = *(ulonglong2*)&es2[jj][it * 8 + 6];
            ull ee[8] = {e0.x, e0.y, e1.x, e1.y, e2.x, e2.y, e3.x, e3.y};
            #pragma unroll
            for (int i = 0; i < 8; ++i) {
                fma2(acc[i][0], ee[i], xv.x);
                fma2(acc[i][1], ee[i], xv.y);
            }
        }
        __syncthreads();
    }
    #pragma unroll
    for (int i = 0; i < 8; ++i) {
        int gi = ibase + it * 8 + i;
        float2 t01 = u2f(acc[i][0]);
        float2 t23 = u2f(acc[i][1]);
        atomicAdd(&g_AGG[((tt*4+0) * Bb + b) * Nn + gi], t01.x);
        atomicAdd(&g_AGG[((tt*4+1) * Bb + b) * Nn + gi], t01.y);
        atomicAdd(&g_AGG[((tt*4+2) * Bb + b) * Nn + gi], t23.x);
        atomicAdd(&g_AGG[((tt*4+3) * Bb + b) * Nn + gi], t23.y);
    }
}

// ---------------- K5: gate GEMM partials per step (f32x2) ----------------
__global__ __launch_bounds__(64) void k5_lin(
    const float* __restrict__ Whr, const float* __restrict__ Whz,
    const float* __restrict__ Whn)
{
    const float* W = (blockIdx.z == 0) ? Whr : ((blockIdx.z == 1) ? Whz : Whn);
    __shared__ __align__(16) float2 ws2[32][132];  // duplicated W [k][n]
    __shared__ __align__(16) float  hs [32][20];   // h [k][b]
    int tid = threadIdx.x;
    int nbase = blockIdx.y * 128;
    int kbase0 = blockIdx.x * 128;
    int nt = tid % 16, bt = tid / 16;

    ull acc[8][2];
    #pragma unroll
    for (int i = 0; i < 8; ++i) { acc[i][0] = 0ull; acc[i][1] = 0ull; }

    for (int kc = 0; kc < 4; ++kc) {
        int kbase = kbase0 + kc * 32;
        #pragma unroll
        for (int p = 0; p < 16; ++p) {
            int v = tid + 64 * p;
            int n = v / 8, kq = v % 8;
            float4 w4 = *(const float4*)&W[(size_t)(nbase + n) * Nn + kbase + kq * 4];
            ws2[kq*4+0][n] = make_float2(w4.x, w4.x);
            ws2[kq*4+1][n] = make_float2(w4.y, w4.y);
            ws2[kq*4+2][n] = make_float2(w4.z, w4.z);
            ws2[kq*4+3][n] = make_float2(w4.w, w4.w);
        }
        #pragma unroll
        for (int p = 0; p < 2; ++p) {
            int v = tid + 64 * p;
            int bb = v / 8, kq = v % 8;
            float4 h4 = *(const float4*)&g_h[bb * Nn + kbase + kq * 4];
            hs[kq*4+0][bb] = h4.x; hs[kq*4+1][bb] = h4.y; hs[kq*4+2][bb] = h4.z; hs[kq*4+3][bb] = h4.w;
        }
        __syncthreads();
        #pragma unroll
        for (int kk = 0; kk < 32; ++kk) {
            ulonglong2 hv = *(ulonglong2*)&hs[kk][bt * 4];
            ulonglong2 w0 = *(ulonglong2*)&ws2[kk][nt * 8 + 0];
            ulonglong2 w1 = *(ulonglong2*)&ws2[kk][nt * 8 + 2];
            ulonglong2 w2 = *(ulonglong2*)&ws2[kk][nt * 8 + 4];
            ulonglong2 w3 = *(ulonglong2*)&ws2[kk][nt * 8 + 6];
            ull wv[8] = {w0.x, w0.y, w1.x, w1.y, w2.x, w2.y, w3.x, w3.y};
            #pragma unroll
            for (int ni = 0; ni < 8; ++ni) {
                fma2(acc[ni][0], wv[ni], hv.x);
                fma2(acc[ni][1], wv[ni], hv.y);
            }
        }
        __syncthreads();
    }
    float* P = g_part + ((size_t)(blockIdx.z * KSPLIT + blockIdx.x) * Bb) * Nn;
    #pragma unroll
    for (int ni = 0; ni < 8; ++ni) {
        int n = nbase + nt * 8 + ni;
        float2 b01 = u2f(acc[ni][0]);
        float2 b23 = u2f(acc[ni][1]);
        P[(bt*4+0) * Nn + n] = b01.x;
        P[(bt*4+1) * Nn + n] = b01.y;
        P[(bt*4+2) * Nn + n] = b23.x;
        P[(bt*4+3) * Nn + n] = b23.y;
    }
}

// ---------------- K6: gate elementwise + partial reduce + h update ----------------
__global__ void k6_gate(const float* __restrict__ bhr, const float* __restrict__ bhz,
                        const float* __restrict__ bhn, int t)
{
    int idx = blockIdx.x * 256 + threadIdx.x;
    if (idx >= Bb * Nn) return;
    int i = idx % Nn;
    float rl = bhr[i], zl = bhz[i], nl = bhn[i];
    #pragma unroll
    for (int p = 0; p < KSPLIT; ++p) {
        rl += g_part[(size_t)(0 * KSPLIT + p) * (Bb * Nn) + idx];
        zl += g_part[(size_t)(1 * KSPLIT + p) * (Bb * Nn) + idx];
        nl += g_part[(size_t)(2 * KSPLIT + p) * (Bb * Nn) + idx];
    }
    float agg = g_AGG[(size_t)t * (Bb * Nn) + idx];
    float h = g_h[idx];
    float r = 1.f / (1.f + expf(-(agg + rl)));
    float z = 1.f / (1.f + expf(-(agg + zl)));
    float n = tanhf(agg + r * nl);
    g_h[idx] = (1.f - z) * n + z * h;
}

// ---------------- K7: out[b] = h[b,:].Wo + bo ----------------
__global__ void k7_out(const float* __restrict__ Wo, const float* __restrict__ bo,
                       float* __restrict__ out)
{
    __shared__ float red[256];
    int b = blockIdx.x, tid = threadIdx.x;
    float s = 0.f;
    for (int i = tid; i < Nn; i += 256) s += g_h[b * Nn + i] * Wo[i];
    red[tid] = s;
    __syncthreads();
    for (int off = 128; off > 0; off >>= 1) {
        if (tid < off) red[tid] += red[tid + off];
        __syncthreads();
    }
    if (tid == 0) out[b] = red[0] + bo[0];
}

extern "C" void kernel_launch(void* const* d_in, const int* in_sizes, int n_in,
                              void* d_out, int out_size) {
    const float* x   = (const float*)d_in[0];
    const int*   adj = (const int*)  d_in[1];
    const float* Wq  = (const float*)d_in[2];
    const float* bq  = (const float*)d_in[3];
    const float* Wk  = (const float*)d_in[4];
    const float* bk  = (const float*)d_in[5];
    const float* Whr = (const float*)d_in[6];
    const float* bhr = (const float*)d_in[7];
    const float* Whz = (const float*)d_in[8];
    const float* bhz = (const float*)d_in[9];
    const float* Whn = (const float*)d_in[10];
    const float* bhn = (const float*)d_in[11];
    const float* Wo  = (const float*)d_in[12];
    const float* bo  = (const float*)d_in[13];
    float* out = (float*)d_out;

    k0_zero<<<(Ss * Bb * Nn + 255) / 256, 256>>>();
    k1_qk<<<dim3(Nn / 128, Ee / 64, Bb), 256>>>(x, Wq, bq, Wk, bk);
    k2_scores<<<dim3(Nn / 128, Nn / 128, Bb), 256>>>(adj);
    k3_xn<<<(Bb * Ss * Nn + 255) / 256, 256>>>(x);
    k4_agg<<<dim3(Nn / 128, 2, Bb), 256>>>();
    for (int t = 0; t < Ss; ++t) {
        k5_lin<<<dim3(KSPLIT, Nn / 128, 3), 64>>>(Whr, Whz, Whn);
        k6_gate<<<(Bb * Nn + 255) / 256, 256>>>(bhr, bhz, bhn, t);
    }
    k7_out<<<Bb, 256>>>(Wo, bo, out);
}

// round 9
// speedup vs baseline: 4.1581x; 4.1581x over previous
#include <cuda_runtime.h>
#include <cuda_bf16.h>
#include <cstdint>

constexpr int Bb = 16, Ss = 64, Nn = 2048, Ee = 256;
constexpr int KSPLIT = 16;

// ---------------- scratch ----------------
__device__ float g_E[(size_t)Bb * Nn * Nn];
__device__ float g_cs[Bb * Nn];
__device__ float g_xn[Bb * Ss * Nn];
__device__ float g_AGG[Ss * Bb * Nn];
__device__ float g_part[3 * KSPLIT * Bb * Nn];
__device__ float g_h[Bb * Nn];
// bf16 hi/lo split of Q,K, row-major [b][n][e]
__device__ uint16_t g_Qh[(size_t)Bb * Nn * Ee];
__device__ uint16_t g_Ql[(size_t)Bb * Nn * Ee];
__device__ uint16_t g_Kh[(size_t)Bb * Nn * Ee];
__device__ uint16_t g_Kl[(size_t)Bb * Nn * Ee];

__device__ __forceinline__ void bf16split(float f, uint16_t& h, uint16_t& l) {
    __nv_bfloat16 hb = __float2bfloat16(f);
    __nv_bfloat16 lb = __float2bfloat16(f - __bfloat162float(hb));
    h = *(uint16_t*)&hb; l = *(uint16_t*)&lb;
}

__device__ __forceinline__ void mma16816(float* c, const uint32_t* a, const uint32_t* bfr) {
    asm volatile(
        "mma.sync.aligned.m16n8k16.row.col.f32.bf16.bf16.f32 "
        "{%0,%1,%2,%3}, {%4,%5,%6,%7}, {%8,%9}, {%0,%1,%2,%3};"
        : "+f"(c[0]), "+f"(c[1]), "+f"(c[2]), "+f"(c[3])
        : "r"(a[0]), "r"(a[1]), "r"(a[2]), "r"(a[3]), "r"(bfr[0]), "r"(bfr[1]));
}

// ---------------- K0: zero cs, h, AGG ----------------
__global__ void k0_zero() {
    int idx = blockIdx.x * 256 + threadIdx.x;
    if (idx < Bb * Nn) { g_cs[idx] = 0.f; g_h[idx] = 0.f; }
    if (idx < Ss * Bb * Nn) g_AGG[idx] = 0.f;
}

// ---------------- K1: Q,K projection -> bf16 hi/lo (row-major) ----------------
__global__ __launch_bounds__(256) void k1_qk(
    const float* __restrict__ x,
    const float* __restrict__ Wq, const float* __restrict__ bq,
    const float* __restrict__ Wk, const float* __restrict__ bk)
{
    __shared__ float As[16][132];
    __shared__ float wqs[64][16];
    __shared__ float wks[64][16];
    int tid = threadIdx.x;
    int b = blockIdx.z, nbase = blockIdx.x * 128, ebase = blockIdx.y * 64;
    int tn = tid % 16, te = tid / 16;

    float4 accq[8], acck[8];
    #pragma unroll
    for (int i = 0; i < 8; ++i) { accq[i] = make_float4(0,0,0,0); acck[i] = make_float4(0,0,0,0); }

    for (int kc = 0; kc < 4; ++kc) {
        int kbase = kc * 16;
        #pragma unroll
        for (int p = 0; p < 2; ++p) {
            int v = tid + 256 * p;
            int k = v / 32, mq = v % 32;
            *(float4*)&As[k][mq * 4] =
                *(const float4*)&x[((size_t)(b * Ss + kbase + k)) * Nn + nbase + mq * 4];
        }
        {
            int e = tid / 4, kq = tid % 4;
            *(float4*)&wqs[e][kq * 4] = *(const float4*)&Wq[(ebase + e) * Ss + kbase + kq * 4];
            *(float4*)&wks[e][kq * 4] = *(const float4*)&Wk[(ebase + e) * Ss + kbase + kq * 4];
        }
        __syncthreads();
        #pragma unroll
        for (int kk = 0; kk < 16; ++kk) {
            float4 alo = *(float4*)&As[kk][tn * 8];
            float4 ahi = *(float4*)&As[kk][tn * 8 + 4];
            float av[8] = {alo.x, alo.y, alo.z, alo.w, ahi.x, ahi.y, ahi.z, ahi.w};
            float wq0 = wqs[te*4+0][kk], wq1 = wqs[te*4+1][kk];
            float wq2 = wqs[te*4+2][kk], wq3 = wqs[te*4+3][kk];
            float wk0 = wks[te*4+0][kk], wk1 = wks[te*4+1][kk];
            float wk2 = wks[te*4+2][kk], wk3 = wks[te*4+3][kk];
            #pragma unroll
            for (int i = 0; i < 8; ++i) {
                accq[i].x += av[i]*wq0; accq[i].y += av[i]*wq1;
                accq[i].z += av[i]*wq2; accq[i].w += av[i]*wq3;
                acck[i].x += av[i]*wk0; acck[i].y += av[i]*wk1;
                acck[i].z += av[i]*wk2; acck[i].w += av[i]*wk3;
            }
        }
        __syncthreads();
    }
    float4 bq4 = *(const float4*)&bq[ebase + te * 4];
    float4 bk4 = *(const float4*)&bk[ebase + te * 4];
    #pragma unroll
    for (int i = 0; i < 8; ++i) {
        int n = nbase + tn * 8 + i;
        size_t o = ((size_t)b * Nn + n) * Ee + ebase + te * 4;
        float qa[4] = {accq[i].x + bq4.x, accq[i].y + bq4.y, accq[i].z + bq4.z, accq[i].w + bq4.w};
        float ka[4] = {acck[i].x + bk4.x, acck[i].y + bk4.y, acck[i].z + bk4.z, acck[i].w + bk4.w};
        ushort4 qh, ql, kh, kl;
        bf16split(qa[0], qh.x, ql.x); bf16split(qa[1], qh.y, ql.y);
        bf16split(qa[2], qh.z, ql.z); bf16split(qa[3], qh.w, ql.w);
        bf16split(ka[0], kh.x, kl.x); bf16split(ka[1], kh.y, kl.y);
        bf16split(ka[2], kh.z, kl.z); bf16split(ka[3], kh.w, kl.w);
        *(ushort4*)&g_Qh[o] = qh; *(ushort4*)&g_Ql[o] = ql;
        *(ushort4*)&g_Kh[o] = kh; *(ushort4*)&g_Kl[o] = kl;
    }
}

// ---------------- K2m: scores via mma.sync bf16-split + mask + exp ----------------
// block 128x128, 8 warps (2m x 4n), warp tile 64x32, K=256 in 16-steps.
// smem rows padded to 12 uint32 (48B) -> conflict-free fragment loads.
__global__ __launch_bounds__(256) void k2m(const int* __restrict__ adj)
{
    __shared__ uint32_t sAh[128 * 12];
    __shared__ uint32_t sAl[128 * 12];
    __shared__ uint32_t sBh[128 * 12];
    __shared__ uint32_t sBl[128 * 12];

    int tid = threadIdx.x;
    int wid = tid / 32, lane = tid % 32;
    int wm = wid >> 2, wn = wid & 3;      // 2 x 4 warps
    int g = lane >> 2, q = lane & 3;
    int b = blockIdx.z, mbase = blockIdx.y * 128, nbase = blockIdx.x * 128;

    const uint16_t* pQh = g_Qh + ((size_t)b * Nn + mbase) * Ee;
    const uint16_t* pQl = g_Ql + ((size_t)b * Nn + mbase) * Ee;
    const uint16_t* pKh = g_Kh + ((size_t)b * Nn + nbase) * Ee;
    const uint16_t* pKl = g_Kl + ((size_t)b * Nn + nbase) * Ee;

    float acc[4][4][4];
    #pragma unroll
    for (int i = 0; i < 4; ++i)
        #pragma unroll
        for (int j = 0; j < 4; ++j)
            #pragma unroll
            for (int c = 0; c < 4; ++c) acc[i][j][c] = 0.f;

    #pragma unroll 1
    for (int ks = 0; ks < 16; ++ks) {
        int kbase = ks * 16;
        #pragma unroll
        for (int p = 0; p < 2; ++p) {
            int v = tid + 256 * p;
            int row = v >> 2, qq = v & 3;
            size_t off = (size_t)row * Ee + kbase + qq * 4;
            uint2 t;
            t = *(const uint2*)(pQh + off); sAh[row*12 + qq*2] = t.x; sAh[row*12 + qq*2 + 1] = t.y;
            t = *(const uint2*)(pQl + off); sAl[row*12 + qq*2] = t.x; sAl[row*12 + qq*2 + 1] = t.y;
            t = *(const uint2*)(pKh + off); sBh[row*12 + qq*2] = t.x; sBh[row*12 + qq*2 + 1] = t.y;
            t = *(const uint2*)(pKl + off); sBl[row*12 + qq*2] = t.x; sBl[row*12 + qq*2 + 1] = t.y;
        }
        __syncthreads();

        uint32_t ah[4][4], al[4][4], bh[4][2], bl[4][2];
        #pragma unroll
        for (int i = 0; i < 4; ++i) {
            int r0 = wm * 64 + i * 16 + g;
            ah[i][0] = sAh[r0*12 + q];       ah[i][1] = sAh[(r0+8)*12 + q];
            ah[i][2] = sAh[r0*12 + q + 4];   ah[i][3] = sAh[(r0+8)*12 + q + 4];
            al[i][0] = sAl[r0*12 + q];       al[i][1] = sAl[(r0+8)*12 + q];
            al[i][2] = sAl[r0*12 + q + 4];   al[i][3] = sAl[(r0+8)*12 + q + 4];
        }
        #pragma unroll
        for (int j = 0; j < 4; ++j) {
            int n0 = wn * 32 + j * 8 + g;
            bh[j][0] = sBh[n0*12 + q];  bh[j][1] = sBh[n0*12 + q + 4];
            bl[j][0] = sBl[n0*12 + q];  bl[j][1] = sBl[n0*12 + q + 4];
        }
        #pragma unroll
        for (int i = 0; i < 4; ++i)
            #pragma unroll
            for (int j = 0; j < 4; ++j) {
                mma16816(acc[i][j], ah[i], bh[j]);
                mma16816(acc[i][j], ah[i], bl[j]);
                mma16816(acc[i][j], al[i], bh[j]);
            }
        __syncthreads();
    }

    // epilogue: mask + exp, write float2 pairs
    #pragma unroll
    for (int i = 0; i < 4; ++i) {
        #pragma unroll
        for (int half = 0; half < 2; ++half) {
            int r = mbase + wm * 64 + i * 16 + g + half * 8;
            const int* adjrow = adj + (size_t)r * Nn;
            float* Erow = g_E + ((size_t)b * Nn + r) * Nn;
            #pragma unroll
            for (int j = 0; j < 4; ++j) {
                int cidx = nbase + wn * 32 + j * 8 + q * 2;
                int2 a2 = *(const int2*)(adjrow + cidx);
                float v0 = acc[i][j][half * 2 + 0];
                float v1 = acc[i][j][half * 2 + 1];
                float2 e2;
                e2.x = (a2.x > 0) ? __expf(v0) : 0.f;
                e2.y = (a2.y > 0) ? __expf(v1) : 0.f;
                *(float2*)(Erow + cidx) = e2;
            }
        }
    }
}

// ---------------- K2b: column sums of E ----------------
__global__ void k2b_cs() {
    int b = blockIdx.z;
    int j = blockIdx.x * 256 + threadIdx.x;
    int iseg = blockIdx.y;
    const float* E = g_E + ((size_t)b * Nn + iseg * 256) * Nn + j;
    float s = 0.f;
    #pragma unroll 8
    for (int i = 0; i < 256; ++i) s += E[(size_t)i * Nn];
    atomicAdd(&g_cs[b * Nn + j], s);
}

// ---------------- K3: xn = x / colsum ----------------
__global__ void k3_xn(const float* __restrict__ x) {
    int idx = blockIdx.x * 256 + threadIdx.x;
    if (idx < Bb * Ss * Nn) {
        int j = idx % Nn;
        int b = idx / (Ss * Nn);
        g_xn[idx] = x[idx] / g_cs[b * Nn + j];
    }
}

// ---------------- K4: AGG[t][b][i] = sum_j E[b,i,j]*xn[b,t,j] ----------------
__global__ __launch_bounds__(256) void k4_agg()
{
    __shared__ float es[32][132];
    __shared__ float xs[32][68];
    int tid = threadIdx.x;
    int b = blockIdx.z, ibase = blockIdx.x * 128, jsp = blockIdx.y;
    int it = tid % 16, tt = tid / 16;

    const float* Eb = g_E + ((size_t)b * Nn + ibase) * Nn;
    const float* xb = g_xn + (size_t)b * Ss * Nn;

    float4 acc[8];
    #pragma unroll
    for (int i = 0; i < 8; ++i) acc[i] = make_float4(0,0,0,0);

    for (int jc = 0; jc < 32; ++jc) {
        int jbase = jsp * 1024 + jc * 32;
        #pragma unroll
        for (int p = 0; p < 4; ++p) {
            int v = tid + 256 * p;
            int i = v / 8, jq = v % 8;
            float4 e4 = *(const float4*)&Eb[(size_t)i * Nn + jbase + jq * 4];
            es[jq*4+0][i] = e4.x; es[jq*4+1][i] = e4.y; es[jq*4+2][i] = e4.z; es[jq*4+3][i] = e4.w;
        }
        #pragma unroll
        for (int p = 0; p < 2; ++p) {
            int v = tid + 256 * p;
            int t = v / 8, jq = v % 8;
            float4 x4 = *(const float4*)&xb[(size_t)t * Nn + jbase + jq * 4];
            xs[jq*4+0][t] = x4.x; xs[jq*4+1][t] = x4.y; xs[jq*4+2][t] = x4.z; xs[jq*4+3][t] = x4.w;
        }
        __syncthreads();
        #pragma unroll
        for (int jj = 0; jj < 32; ++jj) {
            float4 xv = *(float4*)&xs[jj][tt * 4];
            float4 elo = *(float4*)&es[jj][it * 8];
            float4 ehi = *(float4*)&es[jj][it * 8 + 4];
            float ev[8] = {elo.x, elo.y, elo.z, elo.w, ehi.x, ehi.y, ehi.z, ehi.w};
            #pragma unroll
            for (int i = 0; i < 8; ++i) {
                acc[i].x += ev[i]*xv.x; acc[i].y += ev[i]*xv.y;
                acc[i].z += ev[i]*xv.z; acc[i].w += ev[i]*xv.w;
            }
        }
        __syncthreads();
    }
    #pragma unroll
    for (int i = 0; i < 8; ++i) {
        int gi = ibase + it * 8 + i;
        atomicAdd(&g_AGG[((tt*4+0) * Bb + b) * Nn + gi], acc[i].x);
        atomicAdd(&g_AGG[((tt*4+1) * Bb + b) * Nn + gi], acc[i].y);
        atomicAdd(&g_AGG[((tt*4+2) * Bb + b) * Nn + gi], acc[i].z);
        atomicAdd(&g_AGG[((tt*4+3) * Bb + b) * Nn + gi], acc[i].w);
    }
}

// ---------------- K5: gate GEMM partials per step ----------------
__global__ __launch_bounds__(64) void k5_lin(
    const float* __restrict__ Whr, const float* __restrict__ Whz,
    const float* __restrict__ Whn)
{
    const float* W = (blockIdx.z == 0) ? Whr : ((blockIdx.z == 1) ? Whz : Whn);
    __shared__ float ws[32][132];
    __shared__ float hs[32][20];
    int tid = threadIdx.x;
    int nbase = blockIdx.y * 128;
    int kbase0 = blockIdx.x * 128;
    int nt = tid % 16, bt = tid / 16;

    float4 acc[8];
    #pragma unroll
    for (int i = 0; i < 8; ++i) acc[i] = make_float4(0,0,0,0);

    for (int kc = 0; kc < 4; ++kc) {
        int kbase = kbase0 + kc * 32;
        #pragma unroll
        for (int p = 0; p < 16; ++p) {
            int v = tid + 64 * p;
            int n = v / 8, kq = v % 8;
            float4 w4 = *(const float4*)&W[(size_t)(nbase + n) * Nn + kbase + kq * 4];
            ws[kq*4+0][n] = w4.x; ws[kq*4+1][n] = w4.y; ws[kq*4+2][n] = w4.z; ws[kq*4+3][n] = w4.w;
        }
        #pragma unroll
        for (int p = 0; p < 2; ++p) {
            int v = tid + 64 * p;
            int bb = v / 8, kq = v % 8;
            float4 h4 = *(const float4*)&g_h[bb * Nn + kbase + kq * 4];
            hs[kq*4+0][bb] = h4.x; hs[kq*4+1][bb] = h4.y; hs[kq*4+2][bb] = h4.z; hs[kq*4+3][bb] = h4.w;
        }
        __syncthreads();
        #pragma unroll
        for (int kk = 0; kk < 32; ++kk) {
            float4 hv  = *(float4*)&hs[kk][bt * 4];
            float4 wlo = *(float4*)&ws[kk][nt * 8];
            float4 whi = *(float4*)&ws[kk][nt * 8 + 4];
            float wv[8] = {wlo.x, wlo.y, wlo.z, wlo.w, whi.x, whi.y, whi.z, whi.w};
            #pragma unroll
            for (int ni = 0; ni < 8; ++ni) {
                acc[ni].x += wv[ni]*hv.x; acc[ni].y += wv[ni]*hv.y;
                acc[ni].z += wv[ni]*hv.z; acc[ni].w += wv[ni]*hv.w;
            }
        }
        __syncthreads();
    }
    float* P = g_part + ((size_t)(blockIdx.z * KSPLIT + blockIdx.x) * Bb) * Nn;
    #pragma unroll
    for (int ni = 0; ni < 8; ++ni) {
        int n = nbase + nt * 8 + ni;
        P[(bt*4+0) * Nn + n] = acc[ni].x;
        P[(bt*4+1) * Nn + n] = acc[ni].y;
        P[(bt*4+2) * Nn + n] = acc[ni].z;
        P[(bt*4+3) * Nn + n] = acc[ni].w;
    }
}

// ---------------- K6: gates + reduce + h update ----------------
__global__ void k6_gate(const float* __restrict__ bhr, const float* __restrict__ bhz,
                        const float* __restrict__ bhn, int t)
{
    int idx = blockIdx.x * 256 + threadIdx.x;
    if (idx >= Bb * Nn) return;
    int i = idx % Nn;
    float rl = bhr[i], zl = bhz[i], nl = bhn[i];
    #pragma unroll
    for (int p = 0; p < KSPLIT; ++p) {
        rl += g_part[(size_t)(0 * KSPLIT + p) * (Bb * Nn) + idx];
        zl += g_part[(size_t)(1 * KSPLIT + p) * (Bb * Nn) + idx];
        nl += g_part[(size_t)(2 * KSPLIT + p) * (Bb * Nn) + idx];
    }
    float agg = g_AGG[(size_t)t * (Bb * Nn) + idx];
    float h = g_h[idx];
    float r = 1.f / (1.f + expf(-(agg + rl)));
    float z = 1.f / (1.f + expf(-(agg + zl)));
    float n = tanhf(agg + r * nl);
    g_h[idx] = (1.f - z) * n + z * h;
}

// ---------------- K7: out[b] = h[b,:].Wo + bo ----------------
__global__ void k7_out(const float* __restrict__ Wo, const float* __restrict__ bo,
                       float* __restrict__ out)
{
    __shared__ float red[256];
    int b = blockIdx.x, tid = threadIdx.x;
    float s = 0.f;
    for (int i = tid; i < Nn; i += 256) s += g_h[b * Nn + i] * Wo[i];
    red[tid] = s;
    __syncthreads();
    for (int off = 128; off > 0; off >>= 1) {
        if (tid < off) red[tid] += red[tid + off];
        __syncthreads();
    }
    if (tid == 0) out[b] = red[0] + bo[0];
}

extern "C" void kernel_launch(void* const* d_in, const int* in_sizes, int n_in,
                              void* d_out, int out_size) {
    const float* x   = (const float*)d_in[0];
    const int*   adj = (const int*)  d_in[1];
    const float* Wq  = (const float*)d_in[2];
    const float* bq  = (const float*)d_in[3];
    const float* Wk  = (const float*)d_in[4];
    const float* bk  = (const float*)d_in[5];
    const float* Whr = (const float*)d_in[6];
    const float* bhr = (const float*)d_in[7];
    const float* Whz = (const float*)d_in[8];
    const float* bhz = (const float*)d_in[9];
    const float* Whn = (const float*)d_in[10];
    const float* bhn = (const float*)d_in[11];
    const float* Wo  = (const float*)d_in[12];
    const float* bo  = (const float*)d_in[13];
    float* out = (float*)d_out;

    k0_zero<<<(Ss * Bb * Nn + 255) / 256, 256>>>();
    k1_qk<<<dim3(Nn / 128, Ee / 64, Bb), 256>>>(x, Wq, bq, Wk, bk);
    k2m<<<dim3(Nn / 128, Nn / 128, Bb), 256>>>(adj);
    k2b_cs<<<dim3(Nn / 256, 8, Bb), 256>>>();
    k3_xn<<<(Bb * Ss * Nn + 255) / 256, 256>>>(x);
    k4_agg<<<dim3(Nn / 128, 2, Bb), 256>>>();
    for (int t = 0; t < Ss; ++t) {
        k5_lin<<<dim3(KSPLIT, Nn / 128, 3), 64>>>(Whr, Whz, Whn);
        k6_gate<<<(Bb * Nn + 255) / 256, 256>>>(bhr, bhz, bhn, t);
    }
    k7_out<<<Bb, 256>>>(Wo, bo, out);
}

// round 10
// speedup vs baseline: 6.2720x; 1.5084x over previous
#include <cuda_runtime.h>
#include <cuda_bf16.h>
#include <cstdint>

constexpr int Bb = 16, Ss = 64, Nn = 2048, Ee = 256;
constexpr int KS2 = 8;   // k-split for recurrence MMA

// ---------------- scratch ----------------
__device__ float g_E[(size_t)Bb * Nn * Nn];
__device__ float g_cs[Bb * Nn];
__device__ float g_xn[Bb * Ss * Nn];
__device__ float g_AGG[Ss * Bb * Nn];
__device__ float g_part[3 * KS2 * Bb * Nn];
__device__ float g_h[Bb * Nn];
// bf16 hi/lo split of Q,K, row-major [b][n][e]
__device__ uint16_t g_Qh[(size_t)Bb * Nn * Ee];
__device__ uint16_t g_Ql[(size_t)Bb * Nn * Ee];
__device__ uint16_t g_Kh[(size_t)Bb * Nn * Ee];
__device__ uint16_t g_Kl[(size_t)Bb * Nn * Ee];
// W gate weights pre-split to bf16 hi/lo in B-fragment order:
// [gate][ntile(256)][kstep(128)][lane(32)][reg(2)] as uint32 (bf16x2)
__device__ uint32_t g_WFh[3u * 256 * 128 * 64];
__device__ uint32_t g_WFl[3u * 256 * 128 * 64];
// h as bf16 hi/lo, [b][n]
__device__ __nv_bfloat16 g_hh[Bb * Nn];
__device__ __nv_bfloat16 g_hl[Bb * Nn];

__device__ __forceinline__ void bf16split(float f, uint16_t& h, uint16_t& l) {
    __nv_bfloat16 hb = __float2bfloat16(f);
    __nv_bfloat16 lb = __float2bfloat16(f - __bfloat162float(hb));
    h = *(uint16_t*)&hb; l = *(uint16_t*)&lb;
}

__device__ __forceinline__ void mma16816(float* c, const uint32_t* a, const uint32_t* bfr) {
    asm volatile(
        "mma.sync.aligned.m16n8k16.row.col.f32.bf16.bf16.f32 "
        "{%0,%1,%2,%3}, {%4,%5,%6,%7}, {%8,%9}, {%0,%1,%2,%3};"
        : "+f"(c[0]), "+f"(c[1]), "+f"(c[2]), "+f"(c[3])
        : "r"(a[0]), "r"(a[1]), "r"(a[2]), "r"(a[3]), "r"(bfr[0]), "r"(bfr[1]));
}

// ---------------- K0: zero cs, h, hh/hl, AGG ----------------
__global__ void k0_zero() {
    int idx = blockIdx.x * 256 + threadIdx.x;
    if (idx < Bb * Nn) {
        g_cs[idx] = 0.f; g_h[idx] = 0.f;
        g_hh[idx] = __float2bfloat16(0.f);
        g_hl[idx] = __float2bfloat16(0.f);
    }
    if (idx < Ss * Bb * Nn) g_AGG[idx] = 0.f;
}

// ---------------- KW: pre-split gate weights into fragment-ordered bf16 hi/lo ----------------
__global__ void kw_split(const float* __restrict__ Whr, const float* __restrict__ Whz,
                         const float* __restrict__ Whn)
{
    long long t = (long long)blockIdx.x * 256 + threadIdx.x;  // over 3*2048*1024 k-pairs
    if (t >= 3LL * Nn * (Nn / 2)) return;
    int gate = (int)(t / (Nn * (Nn / 2)));
    int rem  = (int)(t % (Nn * (Nn / 2)));
    int n = rem / (Nn / 2);
    int k = (rem % (Nn / 2)) * 2;
    const float* W = (gate == 0) ? Whr : ((gate == 1) ? Whz : Whn);
    float w0 = W[(size_t)n * Nn + k];
    float w1 = W[(size_t)n * Nn + k + 1];
    uint16_t h0, l0, h1, l1;
    bf16split(w0, h0, l0);
    bf16split(w1, h1, l1);
    uint32_t hp = (uint32_t)h0 | ((uint32_t)h1 << 16);
    uint32_t lp = (uint32_t)l0 | ((uint32_t)l1 << 16);
    // fragment index: lane = (n&7)*4 + ((k&7)>>1); reg = (k&15)>>3
    uint32_t idx = ((((uint32_t)gate * 256 + (n >> 3)) * 128 + (k >> 4)) * 32
                    + ((n & 7) * 4 + ((k & 7) >> 1))) * 2 + ((k & 15) >> 3);
    g_WFh[idx] = hp;
    g_WFl[idx] = lp;
}

// ---------------- K1: Q,K projection -> bf16 hi/lo (row-major) ----------------
__global__ __launch_bounds__(256) void k1_qk(
    const float* __restrict__ x,
    const float* __restrict__ Wq, const float* __restrict__ bq,
    const float* __restrict__ Wk, const float* __restrict__ bk)
{
    __shared__ float As[16][132];
    __shared__ float wqs[64][16];
    __shared__ float wks[64][16];
    int tid = threadIdx.x;
    int b = blockIdx.z, nbase = blockIdx.x * 128, ebase = blockIdx.y * 64;
    int tn = tid % 16, te = tid / 16;

    float4 accq[8], acck[8];
    #pragma unroll
    for (int i = 0; i < 8; ++i) { accq[i] = make_float4(0,0,0,0); acck[i] = make_float4(0,0,0,0); }

    for (int kc = 0; kc < 4; ++kc) {
        int kbase = kc * 16;
        #pragma unroll
        for (int p = 0; p < 2; ++p) {
            int v = tid + 256 * p;
            int k = v / 32, mq = v % 32;
            *(float4*)&As[k][mq * 4] =
                *(const float4*)&x[((size_t)(b * Ss + kbase + k)) * Nn + nbase + mq * 4];
        }
        {
            int e = tid / 4, kq = tid % 4;
            *(float4*)&wqs[e][kq * 4] = *(const float4*)&Wq[(ebase + e) * Ss + kbase + kq * 4];
            *(float4*)&wks[e][kq * 4] = *(const float4*)&Wk[(ebase + e) * Ss + kbase + kq * 4];
        }
        __syncthreads();
        #pragma unroll
        for (int kk = 0; kk < 16; ++kk) {
            float4 alo = *(float4*)&As[kk][tn * 8];
            float4 ahi = *(float4*)&As[kk][tn * 8 + 4];
            float av[8] = {alo.x, alo.y, alo.z, alo.w, ahi.x, ahi.y, ahi.z, ahi.w};
            float wq0 = wqs[te*4+0][kk], wq1 = wqs[te*4+1][kk];
            float wq2 = wqs[te*4+2][kk], wq3 = wqs[te*4+3][kk];
            float wk0 = wks[te*4+0][kk], wk1 = wks[te*4+1][kk];
            float wk2 = wks[te*4+2][kk], wk3 = wks[te*4+3][kk];
            #pragma unroll
            for (int i = 0; i < 8; ++i) {
                accq[i].x += av[i]*wq0; accq[i].y += av[i]*wq1;
                accq[i].z += av[i]*wq2; accq[i].w += av[i]*wq3;
                acck[i].x += av[i]*wk0; acck[i].y += av[i]*wk1;
                acck[i].z += av[i]*wk2; acck[i].w += av[i]*wk3;
            }
        }
        __syncthreads();
    }
    float4 bq4 = *(const float4*)&bq[ebase + te * 4];
    float4 bk4 = *(const float4*)&bk[ebase + te * 4];
    #pragma unroll
    for (int i = 0; i < 8; ++i) {
        int n = nbase + tn * 8 + i;
        size_t o = ((size_t)b * Nn + n) * Ee + ebase + te * 4;
        float qa[4] = {accq[i].x + bq4.x, accq[i].y + bq4.y, accq[i].z + bq4.z, accq[i].w + bq4.w};
        float ka[4] = {acck[i].x + bk4.x, acck[i].y + bk4.y, acck[i].z + bk4.z, acck[i].w + bk4.w};
        ushort4 qh, ql, kh, kl;
        bf16split(qa[0], qh.x, ql.x); bf16split(qa[1], qh.y, ql.y);
        bf16split(qa[2], qh.z, ql.z); bf16split(qa[3], qh.w, ql.w);
        bf16split(ka[0], kh.x, kl.x); bf16split(ka[1], kh.y, kl.y);
        bf16split(ka[2], kh.z, kl.z); bf16split(ka[3], kh.w, kl.w);
        *(ushort4*)&g_Qh[o] = qh; *(ushort4*)&g_Ql[o] = ql;
        *(ushort4*)&g_Kh[o] = kh; *(ushort4*)&g_Kl[o] = kl;
    }
}

// ---------------- K2m: scores via mma.sync bf16-split + mask + exp ----------------
__global__ __launch_bounds__(256) void k2m(const int* __restrict__ adj)
{
    __shared__ uint32_t sAh[128 * 12];
    __shared__ uint32_t sAl[128 * 12];
    __shared__ uint32_t sBh[128 * 12];
    __shared__ uint32_t sBl[128 * 12];

    int tid = threadIdx.x;
    int wid = tid / 32, lane = tid % 32;
    int wm = wid >> 2, wn = wid & 3;      // 2 x 4 warps
    int g = lane >> 2, q = lane & 3;
    int b = blockIdx.z, mbase = blockIdx.y * 128, nbase = blockIdx.x * 128;

    const uint16_t* pQh = g_Qh + ((size_t)b * Nn + mbase) * Ee;
    const uint16_t* pQl = g_Ql + ((size_t)b * Nn + mbase) * Ee;
    const uint16_t* pKh = g_Kh + ((size_t)b * Nn + nbase) * Ee;
    const uint16_t* pKl = g_Kl + ((size_t)b * Nn + nbase) * Ee;

    float acc[4][4][4];
    #pragma unroll
    for (int i = 0; i < 4; ++i)
        #pragma unroll
        for (int j = 0; j < 4; ++j)
            #pragma unroll
            for (int c = 0; c < 4; ++c) acc[i][j][c] = 0.f;

    #pragma unroll 1
    for (int ks = 0; ks < 16; ++ks) {
        int kbase = ks * 16;
        #pragma unroll
        for (int p = 0; p < 2; ++p) {
            int v = tid + 256 * p;
            int row = v >> 2, qq = v & 3;
            size_t off = (size_t)row * Ee + kbase + qq * 4;
            uint2 t;
            t = *(const uint2*)(pQh + off); sAh[row*12 + qq*2] = t.x; sAh[row*12 + qq*2 + 1] = t.y;
            t = *(const uint2*)(pQl + off); sAl[row*12 + qq*2] = t.x; sAl[row*12 + qq*2 + 1] = t.y;
            t = *(const uint2*)(pKh + off); sBh[row*12 + qq*2] = t.x; sBh[row*12 + qq*2 + 1] = t.y;
            t = *(const uint2*)(pKl + off); sBl[row*12 + qq*2] = t.x; sBl[row*12 + qq*2 + 1] = t.y;
        }
        __syncthreads();

        uint32_t ah[4][4], al[4][4], bh[4][2], bl[4][2];
        #pragma unroll
        for (int i = 0; i < 4; ++i) {
            int r0 = wm * 64 + i * 16 + g;
            ah[i][0] = sAh[r0*12 + q];       ah[i][1] = sAh[(r0+8)*12 + q];
            ah[i][2] = sAh[r0*12 + q + 4];   ah[i][3] = sAh[(r0+8)*12 + q + 4];
            al[i][0] = sAl[r0*12 + q];       al[i][1] = sAl[(r0+8)*12 + q];
            al[i][2] = sAl[r0*12 + q + 4];   al[i][3] = sAl[(r0+8)*12 + q + 4];
        }
        #pragma unroll
        for (int j = 0; j < 4; ++j) {
            int n0 = wn * 32 + j * 8 + g;
            bh[j][0] = sBh[n0*12 + q];  bh[j][1] = sBh[n0*12 + q + 4];
            bl[j][0] = sBl[n0*12 + q];  bl[j][1] = sBl[n0*12 + q + 4];
        }
        #pragma unroll
        for (int i = 0; i < 4; ++i)
            #pragma unroll
            for (int j = 0; j < 4; ++j) {
                mma16816(acc[i][j], ah[i], bh[j]);
                mma16816(acc[i][j], ah[i], bl[j]);
                mma16816(acc[i][j], al[i], bh[j]);
            }
        __syncthreads();
    }

    #pragma unroll
    for (int i = 0; i < 4; ++i) {
        #pragma unroll
        for (int half = 0; half < 2; ++half) {
            int r = mbase + wm * 64 + i * 16 + g + half * 8;
            const int* adjrow = adj + (size_t)r * Nn;
            float* Erow = g_E + ((size_t)b * Nn + r) * Nn;
            #pragma unroll
            for (int j = 0; j < 4; ++j) {
                int cidx = nbase + wn * 32 + j * 8 + q * 2;
                int2 a2 = *(const int2*)(adjrow + cidx);
                float v0 = acc[i][j][half * 2 + 0];
                float v1 = acc[i][j][half * 2 + 1];
                float2 e2;
                e2.x = (a2.x > 0) ? __expf(v0) : 0.f;
                e2.y = (a2.y > 0) ? __expf(v1) : 0.f;
                *(float2*)(Erow + cidx) = e2;
            }
        }
    }
}

// ---------------- K2b: column sums of E ----------------
__global__ void k2b_cs() {
    int b = blockIdx.z;
    int j = blockIdx.x * 256 + threadIdx.x;
    int iseg = blockIdx.y;
    const float* E = g_E + ((size_t)b * Nn + iseg * 256) * Nn + j;
    float s = 0.f;
    #pragma unroll 8
    for (int i = 0; i < 256; ++i) s += E[(size_t)i * Nn];
    atomicAdd(&g_cs[b * Nn + j], s);
}

// ---------------- K3: xn = x / colsum ----------------
__global__ void k3_xn(const float* __restrict__ x) {
    int idx = blockIdx.x * 256 + threadIdx.x;
    if (idx < Bb * Ss * Nn) {
        int j = idx % Nn;
        int b = idx / (Ss * Nn);
        g_xn[idx] = x[idx] / g_cs[b * Nn + j];
    }
}

// ---------------- K4: AGG[t][b][i] = sum_j E[b,i,j]*xn[b,t,j] ----------------
__global__ __launch_bounds__(256) void k4_agg()
{
    __shared__ float es[32][132];
    __shared__ float xs[32][68];
    int tid = threadIdx.x;
    int b = blockIdx.z, ibase = blockIdx.x * 128, jsp = blockIdx.y;
    int it = tid % 16, tt = tid / 16;

    const float* Eb = g_E + ((size_t)b * Nn + ibase) * Nn;
    const float* xb = g_xn + (size_t)b * Ss * Nn;

    float4 acc[8];
    #pragma unroll
    for (int i = 0; i < 8; ++i) acc[i] = make_float4(0,0,0,0);

    for (int jc = 0; jc < 32; ++jc) {
        int jbase = jsp * 1024 + jc * 32;
        #pragma unroll
        for (int p = 0; p < 4; ++p) {
            int v = tid + 256 * p;
            int i = v / 8, jq = v % 8;
            float4 e4 = *(const float4*)&Eb[(size_t)i * Nn + jbase + jq * 4];
            es[jq*4+0][i] = e4.x; es[jq*4+1][i] = e4.y; es[jq*4+2][i] = e4.z; es[jq*4+3][i] = e4.w;
        }
        #pragma unroll
        for (int p = 0; p < 2; ++p) {
            int v = tid + 256 * p;
            int t = v / 8, jq = v % 8;
            float4 x4 = *(const float4*)&xb[(size_t)t * Nn + jbase + jq * 4];
            xs[jq*4+0][t] = x4.x; xs[jq*4+1][t] = x4.y; xs[jq*4+2][t] = x4.z; xs[jq*4+3][t] = x4.w;
        }
        __syncthreads();
        #pragma unroll
        for (int jj = 0; jj < 32; ++jj) {
            float4 xv = *(float4*)&xs[jj][tt * 4];
            float4 elo = *(float4*)&es[jj][it * 8];
            float4 ehi = *(float4*)&es[jj][it * 8 + 4];
            float ev[8] = {elo.x, elo.y, elo.z, elo.w, ehi.x, ehi.y, ehi.z, ehi.w};
            #pragma unroll
            for (int i = 0; i < 8; ++i) {
                acc[i].x += ev[i]*xv.x; acc[i].y += ev[i]*xv.y;
                acc[i].z += ev[i]*xv.z; acc[i].w += ev[i]*xv.w;
            }
        }
        __syncthreads();
    }
    #pragma unroll
    for (int i = 0; i < 8; ++i) {
        int gi = ibase + it * 8 + i;
        atomicAdd(&g_AGG[((tt*4+0) * Bb + b) * Nn + gi], acc[i].x);
        atomicAdd(&g_AGG[((tt*4+1) * Bb + b) * Nn + gi], acc[i].y);
        atomicAdd(&g_AGG[((tt*4+2) * Bb + b) * Nn + gi], acc[i].z);
        atomicAdd(&g_AGG[((tt*4+3) * Bb + b) * Nn + gi], acc[i].w);
    }
}

// ---------------- K5m: gate GEMM partials via mma.sync ----------------
// part[gate][ks][b][n] = sum_{k in split} h[b,k]*Wg[n,k]
// grid (8 nblk, KS2 ksplit, 3 gate), 256 threads, warp = m16 x n32 x k256
__global__ __launch_bounds__(256) void k5m()
{
    int tid = threadIdx.x;
    int w = tid / 32, lane = tid % 32;
    int ntbase = blockIdx.x * 32 + w * 4;   // 4 n-tiles of 8 per warp
    int ksbase = blockIdx.y * 16;           // 16 k-steps of 16
    int gate = blockIdx.z;

    int r = lane >> 2;            // 0..7
    int kp = (lane & 3) * 2;      // 0,2,4,6

    float acc[4][4];
    #pragma unroll
    for (int j = 0; j < 4; ++j)
        #pragma unroll
        for (int c = 0; c < 4; ++c) acc[j][c] = 0.f;

    #pragma unroll 4
    for (int kst = 0; kst < 16; ++kst) {
        int kstep = ksbase + kst;
        int k0 = kstep * 16;
        uint32_t ah[4], al[4];
        ah[0] = *(const uint32_t*)&g_hh[r * Nn + k0 + kp];
        ah[1] = *(const uint32_t*)&g_hh[(r + 8) * Nn + k0 + kp];
        ah[2] = *(const uint32_t*)&g_hh[r * Nn + k0 + 8 + kp];
        ah[3] = *(const uint32_t*)&g_hh[(r + 8) * Nn + k0 + 8 + kp];
        al[0] = *(const uint32_t*)&g_hl[r * Nn + k0 + kp];
        al[1] = *(const uint32_t*)&g_hl[(r + 8) * Nn + k0 + kp];
        al[2] = *(const uint32_t*)&g_hl[r * Nn + k0 + 8 + kp];
        al[3] = *(const uint32_t*)&g_hl[(r + 8) * Nn + k0 + 8 + kp];
        #pragma unroll
        for (int j = 0; j < 4; ++j) {
            size_t bidx = (((size_t)(gate * 256 + ntbase + j) * 128 + kstep) * 32 + lane) * 2;
            uint2 bh = *(const uint2*)&g_WFh[bidx];
            uint2 bl = *(const uint2*)&g_WFl[bidx];
            mma16816(acc[j], ah, (const uint32_t*)&bh);
            mma16816(acc[j], ah, (const uint32_t*)&bl);
            mma16816(acc[j], al, (const uint32_t*)&bh);
        }
    }

    float* P = g_part + (size_t)(gate * KS2 + blockIdx.y) * (Bb * Nn);
    #pragma unroll
    for (int j = 0; j < 4; ++j) {
        int ncol = (ntbase + j) * 8 + kp;   // (lane&3)*2 within n-tile
        *(float2*)&P[r * Nn + ncol]       = make_float2(acc[j][0], acc[j][1]);
        *(float2*)&P[(r + 8) * Nn + ncol] = make_float2(acc[j][2], acc[j][3]);
    }
}

// ---------------- K6: gates + partial reduce + h update + bf16 split ----------------
__global__ void k6_gate(const float* __restrict__ bhr, const float* __restrict__ bhz,
                        const float* __restrict__ bhn, int t)
{
    int idx = blockIdx.x * 256 + threadIdx.x;
    if (idx >= Bb * Nn) return;
    int i = idx % Nn;
    float rl = bhr[i], zl = bhz[i], nl = bhn[i];
    #pragma unroll
    for (int p = 0; p < KS2; ++p) {
        rl += g_part[(size_t)(0 * KS2 + p) * (Bb * Nn) + idx];
        zl += g_part[(size_t)(1 * KS2 + p) * (Bb * Nn) + idx];
        nl += g_part[(size_t)(2 * KS2 + p) * (Bb * Nn) + idx];
    }
    float agg = g_AGG[(size_t)t * (Bb * Nn) + idx];
    float h = g_h[idx];
    float r = 1.f / (1.f + expf(-(agg + rl)));
    float z = 1.f / (1.f + expf(-(agg + zl)));
    float n = tanhf(agg + r * nl);
    float hn = (1.f - z) * n + z * h;
    g_h[idx] = hn;
    __nv_bfloat16 hb = __float2bfloat16(hn);
    g_hh[idx] = hb;
    g_hl[idx] = __float2bfloat16(hn - __bfloat162float(hb));
}

// ---------------- K7: out[b] = h[b,:].Wo + bo ----------------
__global__ void k7_out(const float* __restrict__ Wo, const float* __restrict__ bo,
                       float* __restrict__ out)
{
    __shared__ float red[256];
    int b = blockIdx.x, tid = threadIdx.x;
    float s = 0.f;
    for (int i = tid; i < Nn; i += 256) s += g_h[b * Nn + i] * Wo[i];
    red[tid] = s;
    __syncthreads();
    for (int off = 128; off > 0; off >>= 1) {
        if (tid < off) red[tid] += red[tid + off];
        __syncthreads();
    }
    if (tid == 0) out[b] = red[0] + bo[0];
}

extern "C" void kernel_launch(void* const* d_in, const int* in_sizes, int n_in,
                              void* d_out, int out_size) {
    const float* x   = (const float*)d_in[0];
    const int*   adj = (const int*)  d_in[1];
    const float* Wq  = (const float*)d_in[2];
    const float* bq  = (const float*)d_in[3];
    const float* Wk  = (const float*)d_in[4];
    const float* bk  = (const float*)d_in[5];
    const float* Whr = (const float*)d_in[6];
    const float* bhr = (const float*)d_in[7];
    const float* Whz = (const float*)d_in[8];
    const float* bhz = (const float*)d_in[9];
    const float* Whn = (const float*)d_in[10];
    const float* bhn = (const float*)d_in[11];
    const float* Wo  = (const float*)d_in[12];
    const float* bo  = (const float*)d_in[13];
    float* out = (float*)d_out;

    k0_zero<<<(Ss * Bb * Nn + 255) / 256, 256>>>();
    kw_split<<<(3 * Nn * (Nn / 2) + 255) / 256, 256>>>(Whr, Whz, Whn);
    k1_qk<<<dim3(Nn / 128, Ee / 64, Bb), 256>>>(x, Wq, bq, Wk, bk);
    k2m<<<dim3(Nn / 128, Nn / 128, Bb), 256>>>(adj);
    k2b_cs<<<dim3(Nn / 256, 8, Bb), 256>>>();
    k3_xn<<<(Bb * Ss * Nn + 255) / 256, 256>>>(x);
    k4_agg<<<dim3(Nn / 128, 2, Bb), 256>>>();
    for (int t = 0; t < Ss; ++t) {
        k5m<<<dim3(8, KS2, 3), 256>>>();
        k6_gate<<<(Bb * Nn + 255) / 256, 256>>>(bhr, bhz, bhn, t);
    }
    k7_out<<<Bb, 256>>>(Wo, bo, out);
}

// round 11
// speedup vs baseline: 6.3287x; 1.0090x over previous
#include <cuda_runtime.h>
#include <cuda_bf16.h>
#include <cstdint>

constexpr int Bb = 16, Ss = 64, Nn = 2048, Ee = 256;
constexpr int KS2 = 8;     // k-split for recurrence MMA
constexpr int NPB = 192;   // persistent blocks (3 gates x 8 nblk x 8 ks)

// ---------------- scratch ----------------
__device__ float g_E[(size_t)Bb * Nn * Nn];
__device__ float g_cs[Bb * Nn];
__device__ float g_xn[Bb * Ss * Nn];
__device__ float g_AGG[Ss * Bb * Nn];
__device__ float g_part[3 * KS2 * Bb * Nn];
__device__ float g_h[Bb * Nn];
__device__ uint16_t g_Qh[(size_t)Bb * Nn * Ee];
__device__ uint16_t g_Ql[(size_t)Bb * Nn * Ee];
__device__ uint16_t g_Kh[(size_t)Bb * Nn * Ee];
__device__ uint16_t g_Kl[(size_t)Bb * Nn * Ee];
// W gate weights pre-split, B-fragment order [gate][ntile][kstep][lane][reg]
__device__ uint32_t g_WFh[3u * 256 * 128 * 64];
__device__ uint32_t g_WFl[3u * 256 * 128 * 64];
__device__ __nv_bfloat16 g_hh[Bb * Nn];
__device__ __nv_bfloat16 g_hl[Bb * Nn];
__device__ unsigned g_barcnt;

__device__ __forceinline__ void bf16split(float f, uint16_t& h, uint16_t& l) {
    __nv_bfloat16 hb = __float2bfloat16(f);
    __nv_bfloat16 lb = __float2bfloat16(f - __bfloat162float(hb));
    h = *(uint16_t*)&hb; l = *(uint16_t*)&lb;
}
__device__ __forceinline__ void mma16816(float* c, const uint32_t* a, const uint32_t* bfr) {
    asm volatile(
        "mma.sync.aligned.m16n8k16.row.col.f32.bf16.bf16.f32 "
        "{%0,%1,%2,%3}, {%4,%5,%6,%7}, {%8,%9}, {%0,%1,%2,%3};"
        : "+f"(c[0]), "+f"(c[1]), "+f"(c[2]), "+f"(c[3])
        : "r"(a[0]), "r"(a[1]), "r"(a[2]), "r"(a[3]), "r"(bfr[0]), "r"(bfr[1]));
}
__device__ __forceinline__ uint32_t smem_u32(const void* p) {
    uint32_t a;
    asm("{ .reg .u64 t; cvta.to.shared.u64 t, %1; cvt.u32.u64 %0, t; }" : "=r"(a) : "l"(p));
    return a;
}
__device__ __forceinline__ void ldsm4(uint32_t* d, uint32_t addr) {
    asm volatile("ldmatrix.sync.aligned.m8n8.x4.shared.b16 {%0,%1,%2,%3}, [%4];"
        : "=r"(d[0]), "=r"(d[1]), "=r"(d[2]), "=r"(d[3]) : "r"(addr));
}

// ---------------- K0: zero cs, h, hh/hl, AGG, barrier ----------------
__global__ void k0_zero() {
    int idx = blockIdx.x * 256 + threadIdx.x;
    if (idx == 0) g_barcnt = 0u;
    if (idx < Bb * Nn) {
        g_cs[idx] = 0.f; g_h[idx] = 0.f;
        g_hh[idx] = __float2bfloat16(0.f);
        g_hl[idx] = __float2bfloat16(0.f);
    }
    if (idx < Ss * Bb * Nn) g_AGG[idx] = 0.f;
}

// ---------------- KW: pre-split gate weights (fragment order) ----------------
__global__ void kw_split(const float* __restrict__ Whr, const float* __restrict__ Whz,
                         const float* __restrict__ Whn)
{
    long long t = (long long)blockIdx.x * 256 + threadIdx.x;
    if (t >= 3LL * Nn * (Nn / 2)) return;
    int gate = (int)(t / (Nn * (Nn / 2)));
    int rem  = (int)(t % (Nn * (Nn / 2)));
    int n = rem / (Nn / 2);
    int k = (rem % (Nn / 2)) * 2;
    const float* W = (gate == 0) ? Whr : ((gate == 1) ? Whz : Whn);
    float w0 = W[(size_t)n * Nn + k];
    float w1 = W[(size_t)n * Nn + k + 1];
    uint16_t h0, l0, h1, l1;
    bf16split(w0, h0, l0);
    bf16split(w1, h1, l1);
    uint32_t hp = (uint32_t)h0 | ((uint32_t)h1 << 16);
    uint32_t lp = (uint32_t)l0 | ((uint32_t)l1 << 16);
    uint32_t idx = ((((uint32_t)gate * 256 + (n >> 3)) * 128 + (k >> 4)) * 32
                    + ((n & 7) * 4 + ((k & 7) >> 1))) * 2 + ((k & 15) >> 3);
    g_WFh[idx] = hp;
    g_WFl[idx] = lp;
}

// ---------------- K1: Q,K projection -> bf16 hi/lo ----------------
__global__ __launch_bounds__(256) void k1_qk(
    const float* __restrict__ x,
    const float* __restrict__ Wq, const float* __restrict__ bq,
    const float* __restrict__ Wk, const float* __restrict__ bk)
{
    __shared__ float As[16][132];
    __shared__ float wqs[64][16];
    __shared__ float wks[64][16];
    int tid = threadIdx.x;
    int b = blockIdx.z, nbase = blockIdx.x * 128, ebase = blockIdx.y * 64;
    int tn = tid % 16, te = tid / 16;

    float4 accq[8], acck[8];
    #pragma unroll
    for (int i = 0; i < 8; ++i) { accq[i] = make_float4(0,0,0,0); acck[i] = make_float4(0,0,0,0); }

    for (int kc = 0; kc < 4; ++kc) {
        int kbase = kc * 16;
        #pragma unroll
        for (int p = 0; p < 2; ++p) {
            int v = tid + 256 * p;
            int k = v / 32, mq = v % 32;
            *(float4*)&As[k][mq * 4] =
                *(const float4*)&x[((size_t)(b * Ss + kbase + k)) * Nn + nbase + mq * 4];
        }
        {
            int e = tid / 4, kq = tid % 4;
            *(float4*)&wqs[e][kq * 4] = *(const float4*)&Wq[(ebase + e) * Ss + kbase + kq * 4];
            *(float4*)&wks[e][kq * 4] = *(const float4*)&Wk[(ebase + e) * Ss + kbase + kq * 4];
        }
        __syncthreads();
        #pragma unroll
        for (int kk = 0; kk < 16; ++kk) {
            float4 alo = *(float4*)&As[kk][tn * 8];
            float4 ahi = *(float4*)&As[kk][tn * 8 + 4];
            float av[8] = {alo.x, alo.y, alo.z, alo.w, ahi.x, ahi.y, ahi.z, ahi.w};
            float wq0 = wqs[te*4+0][kk], wq1 = wqs[te*4+1][kk];
            float wq2 = wqs[te*4+2][kk], wq3 = wqs[te*4+3][kk];
            float wk0 = wks[te*4+0][kk], wk1 = wks[te*4+1][kk];
            float wk2 = wks[te*4+2][kk], wk3 = wks[te*4+3][kk];
            #pragma unroll
            for (int i = 0; i < 8; ++i) {
                accq[i].x += av[i]*wq0; accq[i].y += av[i]*wq1;
                accq[i].z += av[i]*wq2; accq[i].w += av[i]*wq3;
                acck[i].x += av[i]*wk0; acck[i].y += av[i]*wk1;
                acck[i].z += av[i]*wk2; acck[i].w += av[i]*wk3;
            }
        }
        __syncthreads();
    }
    float4 bq4 = *(const float4*)&bq[ebase + te * 4];
    float4 bk4 = *(const float4*)&bk[ebase + te * 4];
    #pragma unroll
    for (int i = 0; i < 8; ++i) {
        int n = nbase + tn * 8 + i;
        size_t o = ((size_t)b * Nn + n) * Ee + ebase + te * 4;
        float qa[4] = {accq[i].x + bq4.x, accq[i].y + bq4.y, accq[i].z + bq4.z, accq[i].w + bq4.w};
        float ka[4] = {acck[i].x + bk4.x, acck[i].y + bk4.y, acck[i].z + bk4.z, acck[i].w + bk4.w};
        ushort4 qh, ql, kh, kl;
        bf16split(qa[0], qh.x, ql.x); bf16split(qa[1], qh.y, ql.y);
        bf16split(qa[2], qh.z, ql.z); bf16split(qa[3], qh.w, ql.w);
        bf16split(ka[0], kh.x, kl.x); bf16split(ka[1], kh.y, kl.y);
        bf16split(ka[2], kh.z, kl.z); bf16split(ka[3], kh.w, kl.w);
        *(ushort4*)&g_Qh[o] = qh; *(ushort4*)&g_Ql[o] = ql;
        *(ushort4*)&g_Kh[o] = kh; *(ushort4*)&g_Kl[o] = kl;
    }
}

// ---------------- K2m: scores via mma.sync + ldmatrix ----------------
__global__ __launch_bounds__(256) void k2m(const int* __restrict__ adj)
{
    __shared__ uint32_t sAh[128 * 12];
    __shared__ uint32_t sAl[128 * 12];
    __shared__ uint32_t sBh[128 * 12];
    __shared__ uint32_t sBl[128 * 12];

    int tid = threadIdx.x;
    int wid = tid / 32, lane = tid % 32;
    int wm = wid >> 2, wn = wid & 3;
    int g = lane >> 2, q = lane & 3;
    int b = blockIdx.z, mbase = blockIdx.y * 128, nbase = blockIdx.x * 128;

    const uint16_t* pQh = g_Qh + ((size_t)b * Nn + mbase) * Ee;
    const uint16_t* pQl = g_Ql + ((size_t)b * Nn + mbase) * Ee;
    const uint16_t* pKh = g_Kh + ((size_t)b * Nn + nbase) * Ee;
    const uint16_t* pKl = g_Kl + ((size_t)b * Nn + nbase) * Ee;

    uint32_t aAh = smem_u32(sAh), aAl = smem_u32(sAl);
    uint32_t aBh = smem_u32(sBh), aBl = smem_u32(sBl);

    // ldmatrix address components
    int lrowA = lane & 15;                 // row within 16
    int lcolA = (lane & 16) ? 4 : 0;       // +16B for k8-15
    int browB = lane & 7;
    int bselB = (lane & 8) ? 4 : 0;        // +16B for k8-15
    int bhalfB = (lane & 16) ? 8 : 0;      // second n8 tile

    float acc[4][4][4];
    #pragma unroll
    for (int i = 0; i < 4; ++i)
        #pragma unroll
        for (int j = 0; j < 4; ++j)
            #pragma unroll
            for (int c = 0; c < 4; ++c) acc[i][j][c] = 0.f;

    #pragma unroll 1
    for (int ks = 0; ks < 16; ++ks) {
        int kbase = ks * 16;
        #pragma unroll
        for (int p = 0; p < 2; ++p) {
            int v = tid + 256 * p;
            int row = v >> 2, qq = v & 3;
            size_t off = (size_t)row * Ee + kbase + qq * 4;
            uint2 t;
            t = *(const uint2*)(pQh + off); sAh[row*12 + qq*2] = t.x; sAh[row*12 + qq*2 + 1] = t.y;
            t = *(const uint2*)(pQl + off); sAl[row*12 + qq*2] = t.x; sAl[row*12 + qq*2 + 1] = t.y;
            t = *(const uint2*)(pKh + off); sBh[row*12 + qq*2] = t.x; sBh[row*12 + qq*2 + 1] = t.y;
            t = *(const uint2*)(pKl + off); sBl[row*12 + qq*2] = t.x; sBl[row*12 + qq*2 + 1] = t.y;
        }
        __syncthreads();

        uint32_t ah[4][4], al[4][4], bh[4][2], bl[4][2];
        #pragma unroll
        for (int i = 0; i < 4; ++i) {
            uint32_t offA = (uint32_t)(((wm * 64 + i * 16 + lrowA) * 12 + lcolA) * 4);
            ldsm4(ah[i], aAh + offA);
            ldsm4(al[i], aAl + offA);
        }
        #pragma unroll
        for (int jj = 0; jj < 2; ++jj) {
            uint32_t offB = (uint32_t)(((wn * 32 + jj * 16 + bhalfB + browB) * 12 + bselB) * 4);
            uint32_t th[4], tl[4];
            ldsm4(th, aBh + offB);
            ldsm4(tl, aBl + offB);
            bh[2*jj][0] = th[0]; bh[2*jj][1] = th[1]; bh[2*jj+1][0] = th[2]; bh[2*jj+1][1] = th[3];
            bl[2*jj][0] = tl[0]; bl[2*jj][1] = tl[1]; bl[2*jj+1][0] = tl[2]; bl[2*jj+1][1] = tl[3];
        }
        #pragma unroll
        for (int i = 0; i < 4; ++i)
            #pragma unroll
            for (int j = 0; j < 4; ++j) {
                mma16816(acc[i][j], ah[i], bh[j]);
                mma16816(acc[i][j], ah[i], bl[j]);
                mma16816(acc[i][j], al[i], bh[j]);
            }
        __syncthreads();
    }

    #pragma unroll
    for (int i = 0; i < 4; ++i) {
        #pragma unroll
        for (int half = 0; half < 2; ++half) {
            int r = mbase + wm * 64 + i * 16 + g + half * 8;
            const int* adjrow = adj + (size_t)r * Nn;
            float* Erow = g_E + ((size_t)b * Nn + r) * Nn;
            #pragma unroll
            for (int j = 0; j < 4; ++j) {
                int cidx = nbase + wn * 32 + j * 8 + q * 2;
                int2 a2 = *(const int2*)(adjrow + cidx);
                float v0 = acc[i][j][half * 2 + 0];
                float v1 = acc[i][j][half * 2 + 1];
                float2 e2;
                e2.x = (a2.x > 0) ? __expf(v0) : 0.f;
                e2.y = (a2.y > 0) ? __expf(v1) : 0.f;
                *(float2*)(Erow + cidx) = e2;
            }
        }
    }
}

// ---------------- K2b: column sums of E ----------------
__global__ void k2b_cs() {
    int b = blockIdx.z;
    int j = blockIdx.x * 256 + threadIdx.x;
    int iseg = blockIdx.y;
    const float* E = g_E + ((size_t)b * Nn + iseg * 256) * Nn + j;
    float s = 0.f;
    #pragma unroll 8
    for (int i = 0; i < 256; ++i) s += E[(size_t)i * Nn];
    atomicAdd(&g_cs[b * Nn + j], s);
}

// ---------------- K3: xn = x / colsum ----------------
__global__ void k3_xn(const float* __restrict__ x) {
    int idx = blockIdx.x * 256 + threadIdx.x;
    if (idx < Bb * Ss * Nn) {
        int j = idx % Nn;
        int b = idx / (Ss * Nn);
        g_xn[idx] = x[idx] / g_cs[b * Nn + j];
    }
}

// ---------------- K4: AGG[t][b][i] = sum_j E[b,i,j]*xn[b,t,j] ----------------
__global__ __launch_bounds__(256) void k4_agg()
{
    __shared__ float es[32][132];
    __shared__ float xs[32][68];
    int tid = threadIdx.x;
    int b = blockIdx.z, ibase = blockIdx.x * 128, jsp = blockIdx.y;
    int it = tid % 16, tt = tid / 16;

    const float* Eb = g_E + ((size_t)b * Nn + ibase) * Nn;
    const float* xb = g_xn + (size_t)b * Ss * Nn;

    float4 acc[8];
    #pragma unroll
    for (int i = 0; i < 8; ++i) acc[i] = make_float4(0,0,0,0);

    for (int jc = 0; jc < 32; ++jc) {
        int jbase = jsp * 1024 + jc * 32;
        #pragma unroll
        for (int p = 0; p < 4; ++p) {
            int v = tid + 256 * p;
            int i = v / 8, jq = v % 8;
            float4 e4 = *(const float4*)&Eb[(size_t)i * Nn + jbase + jq * 4];
            es[jq*4+0][i] = e4.x; es[jq*4+1][i] = e4.y; es[jq*4+2][i] = e4.z; es[jq*4+3][i] = e4.w;
        }
        #pragma unroll
        for (int p = 0; p < 2; ++p) {
            int v = tid + 256 * p;
            int t = v / 8, jq = v % 8;
            float4 x4 = *(const float4*)&xb[(size_t)t * Nn + jbase + jq * 4];
            xs[jq*4+0][t] = x4.x; xs[jq*4+1][t] = x4.y; xs[jq*4+2][t] = x4.z; xs[jq*4+3][t] = x4.w;
        }
        __syncthreads();
        #pragma unroll
        for (int jj = 0; jj < 32; ++jj) {
            float4 xv = *(float4*)&xs[jj][tt * 4];
            float4 elo = *(float4*)&es[jj][it * 8];
            float4 ehi = *(float4*)&es[jj][it * 8 + 4];
            float ev[8] = {elo.x, elo.y, elo.z, elo.w, ehi.x, ehi.y, ehi.z, ehi.w};
            #pragma unroll
            for (int i = 0; i < 8; ++i) {
                acc[i].x += ev[i]*xv.x; acc[i].y += ev[i]*xv.y;
                acc[i].z += ev[i]*xv.z; acc[i].w += ev[i]*xv.w;
            }
        }
        __syncthreads();
    }
    #pragma unroll
    for (int i = 0; i < 8; ++i) {
        int gi = ibase + it * 8 + i;
        atomicAdd(&g_AGG[((tt*4+0) * Bb + b) * Nn + gi], acc[i].x);
        atomicAdd(&g_AGG[((tt*4+1) * Bb + b) * Nn + gi], acc[i].y);
        atomicAdd(&g_AGG[((tt*4+2) * Bb + b) * Nn + gi], acc[i].z);
        atomicAdd(&g_AGG[((tt*4+3) * Bb + b) * Nn + gi], acc[i].w);
    }
}

// ---------------- K5p: persistent recurrence (all 64 steps) ----------------
// 192 blocks co-resident; software grid barrier (monotonic counter).
__global__ __launch_bounds__(256, 2) void k5p(
    const float* __restrict__ bhr, const float* __restrict__ bhz,
    const float* __restrict__ bhn)
{
    int tid = threadIdx.x;
    int bid = blockIdx.x;
    int nblkI = bid & 7;
    int ksI   = (bid >> 3) & 7;
    int gate  = bid >> 6;
    int w = tid / 32, lane = tid % 32;
    int ntbase = nblkI * 32 + w * 4;
    int ksbase = ksI * 16;
    int r = lane >> 2;
    int kp = (lane & 3) * 2;

    // gate-phase ownership
    int gid = bid * 256 + tid;
    float rb = 0.f, zb = 0.f, nb = 0.f, hloc = 0.f;
    bool own = (gid < Bb * Nn);
    if (own) { int i = gid % Nn; rb = bhr[i]; zb = bhz[i]; nb = bhn[i]; }

    float* Pme = g_part + (size_t)(gate * KS2 + ksI) * (Bb * Nn);
    unsigned target = 0;

    for (int t = 0; t < Ss; ++t) {
        // ---- GEMM phase: partials for this (gate, ks, n-range) ----
        float acc[4][4];
        #pragma unroll
        for (int j = 0; j < 4; ++j)
            #pragma unroll
            for (int c = 0; c < 4; ++c) acc[j][c] = 0.f;

        #pragma unroll 4
        for (int kst = 0; kst < 16; ++kst) {
            int kstep = ksbase + kst;
            int k0 = kstep * 16;
            uint32_t ah[4], al[4];
            ah[0] = __ldcg((const uint32_t*)&g_hh[r * Nn + k0 + kp]);
            ah[1] = __ldcg((const uint32_t*)&g_hh[(r + 8) * Nn + k0 + kp]);
            ah[2] = __ldcg((const uint32_t*)&g_hh[r * Nn + k0 + 8 + kp]);
            ah[3] = __ldcg((const uint32_t*)&g_hh[(r + 8) * Nn + k0 + 8 + kp]);
            al[0] = __ldcg((const uint32_t*)&g_hl[r * Nn + k0 + kp]);
            al[1] = __ldcg((const uint32_t*)&g_hl[(r + 8) * Nn + k0 + kp]);
            al[2] = __ldcg((const uint32_t*)&g_hl[r * Nn + k0 + 8 + kp]);
            al[3] = __ldcg((const uint32_t*)&g_hl[(r + 8) * Nn + k0 + 8 + kp]);
            #pragma unroll
            for (int j = 0; j < 4; ++j) {
                size_t bidx = (((size_t)(gate * 256 + ntbase + j) * 128 + kstep) * 32 + lane) * 2;
                uint2 bh = *(const uint2*)&g_WFh[bidx];
                uint2 bl = *(const uint2*)&g_WFl[bidx];
                mma16816(acc[j], ah, (const uint32_t*)&bh);
                mma16816(acc[j], ah, (const uint32_t*)&bl);
                mma16816(acc[j], al, (const uint32_t*)&bh);
            }
        }
        #pragma unroll
        for (int j = 0; j < 4; ++j) {
            int ncol = (ntbase + j) * 8 + kp;
            *(float2*)&Pme[r * Nn + ncol]       = make_float2(acc[j][0], acc[j][1]);
            *(float2*)&Pme[(r + 8) * Nn + ncol] = make_float2(acc[j][2], acc[j][3]);
        }

        // ---- barrier 1 ----
        target += NPB;
        __syncthreads();
        if (tid == 0) {
            __threadfence();
            atomicAdd(&g_barcnt, 1u);
            while (*(volatile unsigned*)&g_barcnt < target) __nanosleep(64);
        }
        __syncthreads();

        // ---- gate phase ----
        if (own) {
            float rl = rb, zl = zb, nl = nb;
            #pragma unroll
            for (int p = 0; p < KS2; ++p) {
                rl += __ldcg(&g_part[(size_t)(0 * KS2 + p) * (Bb * Nn) + gid]);
                zl += __ldcg(&g_part[(size_t)(1 * KS2 + p) * (Bb * Nn) + gid]);
                nl += __ldcg(&g_part[(size_t)(2 * KS2 + p) * (Bb * Nn) + gid]);
            }
            float agg = g_AGG[(size_t)t * (Bb * Nn) + gid];
            float rr = 1.f / (1.f + expf(-(agg + rl)));
            float zz = 1.f / (1.f + expf(-(agg + zl)));
            float nn2 = tanhf(agg + rr * nl);
            float hn = (1.f - zz) * nn2 + zz * hloc;
            hloc = hn;
            __nv_bfloat16 hb = __float2bfloat16(hn);
            g_hh[gid] = hb;
            g_hl[gid] = __float2bfloat16(hn - __bfloat162float(hb));
            if (t == Ss - 1) g_h[gid] = hn;
        }

        // ---- barrier 2 ----
        target += NPB;
        __syncthreads();
        if (tid == 0) {
            __threadfence();
            atomicAdd(&g_barcnt, 1u);
            while (*(volatile unsigned*)&g_barcnt < target) __nanosleep(64);
        }
        __syncthreads();
    }
}

// ---------------- K7: out[b] = h[b,:].Wo + bo ----------------
__global__ void k7_out(const float* __restrict__ Wo, const float* __restrict__ bo,
                       float* __restrict__ out)
{
    __shared__ float red[256];
    int b = blockIdx.x, tid = threadIdx.x;
    float s = 0.f;
    for (int i = tid; i < Nn; i += 256) s += g_h[b * Nn + i] * Wo[i];
    red[tid] = s;
    __syncthreads();
    for (int off = 128; off > 0; off >>= 1) {
        if (tid < off) red[tid] += red[tid + off];
        __syncthreads();
    }
    if (tid == 0) out[b] = red[0] + bo[0];
}

extern "C" void kernel_launch(void* const* d_in, const int* in_sizes, int n_in,
                              void* d_out, int out_size) {
    const float* x   = (const float*)d_in[0];
    const int*   adj = (const int*)  d_in[1];
    const float* Wq  = (const float*)d_in[2];
    const float* bq  = (const float*)d_in[3];
    const float* Wk  = (const float*)d_in[4];
    const float* bk  = (const float*)d_in[5];
    const float* Whr = (const float*)d_in[6];
    const float* bhr = (const float*)d_in[7];
    const float* Whz = (const float*)d_in[8];
    const float* bhz = (const float*)d_in[9];
    const float* Whn = (const float*)d_in[10];
    const float* bhn = (const float*)d_in[11];
    const float* Wo  = (const float*)d_in[12];
    const float* bo  = (const float*)d_in[13];
    float* out = (float*)d_out;

    k0_zero<<<(Ss * Bb * Nn + 255) / 256, 256>>>();
    kw_split<<<(3 * Nn * (Nn / 2) + 255) / 256, 256>>>(Whr, Whz, Whn);
    k1_qk<<<dim3(Nn / 128, Ee / 64, Bb), 256>>>(x, Wq, bq, Wk, bk);
    k2m<<<dim3(Nn / 128, Nn / 128, Bb), 256>>>(adj);
    k2b_cs<<<dim3(Nn / 256, 8, Bb), 256>>>();
    k3_xn<<<(Bb * Ss * Nn + 255) / 256, 256>>>(x);
    k4_agg<<<dim3(Nn / 128, 2, Bb), 256>>>();
    k5p<<<NPB, 256>>>(bhr, bhz, bhn);
    k7_out<<<Bb, 256>>>(Wo, bo, out);
}

// round 12
// speedup vs baseline: 7.0431x; 1.1129x over previous
#include <cuda_runtime.h>
#include <cuda_bf16.h>
#include <cstdint>

constexpr int Bb = 16, Ss = 64, Nn = 2048, Ee = 256;
constexpr int KS2 = 8;     // k-split for recurrence MMA
constexpr int NPB = 192;   // persistent blocks (3 gates x 8 nblk x 8 ks)

// ---------------- scratch ----------------
__device__ uint16_t g_Eh[(size_t)Bb * Nn * Nn];   // bf16 hi of exp(scores)
__device__ uint16_t g_El[(size_t)Bb * Nn * Nn];   // bf16 lo
__device__ float g_cs[Bb * Nn];
__device__ uint16_t g_xnh[Bb * Ss * Nn];
__device__ uint16_t g_xnl[Bb * Ss * Nn];
__device__ float g_AGG[Ss * Bb * Nn];
__device__ float g_part[3 * KS2 * Bb * Nn];
__device__ float g_h[Bb * Nn];
__device__ uint16_t g_Qh[(size_t)Bb * Nn * Ee];
__device__ uint16_t g_Ql[(size_t)Bb * Nn * Ee];
__device__ uint16_t g_Kh[(size_t)Bb * Nn * Ee];
__device__ uint16_t g_Kl[(size_t)Bb * Nn * Ee];
// W gate weights pre-split, B-fragment order [gate][ntile][kstep][lane][reg]
__device__ uint32_t g_WFh[3u * 256 * 128 * 64];
__device__ uint32_t g_WFl[3u * 256 * 128 * 64];
__device__ __nv_bfloat16 g_hh[Bb * Nn];
__device__ __nv_bfloat16 g_hl[Bb * Nn];
__device__ unsigned g_barcnt;

__device__ __forceinline__ void bf16split(float f, uint16_t& h, uint16_t& l) {
    __nv_bfloat16 hb = __float2bfloat16(f);
    __nv_bfloat16 lb = __float2bfloat16(f - __bfloat162float(hb));
    h = *(uint16_t*)&hb; l = *(uint16_t*)&lb;
}
__device__ __forceinline__ void mma16816(float* c, const uint32_t* a, const uint32_t* bfr) {
    asm volatile(
        "mma.sync.aligned.m16n8k16.row.col.f32.bf16.bf16.f32 "
        "{%0,%1,%2,%3}, {%4,%5,%6,%7}, {%8,%9}, {%0,%1,%2,%3};"
        : "+f"(c[0]), "+f"(c[1]), "+f"(c[2]), "+f"(c[3])
        : "r"(a[0]), "r"(a[1]), "r"(a[2]), "r"(a[3]), "r"(bfr[0]), "r"(bfr[1]));
}
__device__ __forceinline__ uint32_t smem_u32(const void* p) {
    uint32_t a;
    asm("{ .reg .u64 t; cvta.to.shared.u64 t, %1; cvt.u32.u64 %0, t; }" : "=r"(a) : "l"(p));
    return a;
}
__device__ __forceinline__ void ldsm4(uint32_t* d, uint32_t addr) {
    asm volatile("ldmatrix.sync.aligned.m8n8.x4.shared.b16 {%0,%1,%2,%3}, [%4];"
        : "=r"(d[0]), "=r"(d[1]), "=r"(d[2]), "=r"(d[3]) : "r"(addr));
}

// ---------------- K0: zero cs, h, hh/hl, barrier ----------------
__global__ void k0_zero() {
    int idx = blockIdx.x * 256 + threadIdx.x;
    if (idx == 0) g_barcnt = 0u;
    if (idx < Bb * Nn) {
        g_cs[idx] = 0.f; g_h[idx] = 0.f;
        g_hh[idx] = __float2bfloat16(0.f);
        g_hl[idx] = __float2bfloat16(0.f);
    }
}

// ---------------- KW: pre-split gate weights (fragment order) ----------------
__global__ void kw_split(const float* __restrict__ Whr, const float* __restrict__ Whz,
                         const float* __restrict__ Whn)
{
    long long t = (long long)blockIdx.x * 256 + threadIdx.x;
    if (t >= 3LL * Nn * (Nn / 2)) return;
    int gate = (int)(t / (Nn * (Nn / 2)));
    int rem  = (int)(t % (Nn * (Nn / 2)));
    int n = rem / (Nn / 2);
    int k = (rem % (Nn / 2)) * 2;
    const float* W = (gate == 0) ? Whr : ((gate == 1) ? Whz : Whn);
    float w0 = W[(size_t)n * Nn + k];
    float w1 = W[(size_t)n * Nn + k + 1];
    uint16_t h0, l0, h1, l1;
    bf16split(w0, h0, l0);
    bf16split(w1, h1, l1);
    uint32_t hp = (uint32_t)h0 | ((uint32_t)h1 << 16);
    uint32_t lp = (uint32_t)l0 | ((uint32_t)l1 << 16);
    uint32_t idx = ((((uint32_t)gate * 256 + (n >> 3)) * 128 + (k >> 4)) * 32
                    + ((n & 7) * 4 + ((k & 7) >> 1))) * 2 + ((k & 15) >> 3);
    g_WFh[idx] = hp;
    g_WFl[idx] = lp;
}

// ---------------- K1: Q,K projection -> bf16 hi/lo ----------------
__global__ __launch_bounds__(256) void k1_qk(
    const float* __restrict__ x,
    const float* __restrict__ Wq, const float* __restrict__ bq,
    const float* __restrict__ Wk, const float* __restrict__ bk)
{
    __shared__ float As[16][132];
    __shared__ float wqs[64][16];
    __shared__ float wks[64][16];
    int tid = threadIdx.x;
    int b = blockIdx.z, nbase = blockIdx.x * 128, ebase = blockIdx.y * 64;
    int tn = tid % 16, te = tid / 16;

    float4 accq[8], acck[8];
    #pragma unroll
    for (int i = 0; i < 8; ++i) { accq[i] = make_float4(0,0,0,0); acck[i] = make_float4(0,0,0,0); }

    for (int kc = 0; kc < 4; ++kc) {
        int kbase = kc * 16;
        #pragma unroll
        for (int p = 0; p < 2; ++p) {
            int v = tid + 256 * p;
            int k = v / 32, mq = v % 32;
            *(float4*)&As[k][mq * 4] =
                *(const float4*)&x[((size_t)(b * Ss + kbase + k)) * Nn + nbase + mq * 4];
        }
        {
            int e = tid / 4, kq = tid % 4;
            *(float4*)&wqs[e][kq * 4] = *(const float4*)&Wq[(ebase + e) * Ss + kbase + kq * 4];
            *(float4*)&wks[e][kq * 4] = *(const float4*)&Wk[(ebase + e) * Ss + kbase + kq * 4];
        }
        __syncthreads();
        #pragma unroll
        for (int kk = 0; kk < 16; ++kk) {
            float4 alo = *(float4*)&As[kk][tn * 8];
            float4 ahi = *(float4*)&As[kk][tn * 8 + 4];
            float av[8] = {alo.x, alo.y, alo.z, alo.w, ahi.x, ahi.y, ahi.z, ahi.w};
            float wq0 = wqs[te*4+0][kk], wq1 = wqs[te*4+1][kk];
            float wq2 = wqs[te*4+2][kk], wq3 = wqs[te*4+3][kk];
            float wk0 = wks[te*4+0][kk], wk1 = wks[te*4+1][kk];
            float wk2 = wks[te*4+2][kk], wk3 = wks[te*4+3][kk];
            #pragma unroll
            for (int i = 0; i < 8; ++i) {
                accq[i].x += av[i]*wq0; accq[i].y += av[i]*wq1;
                accq[i].z += av[i]*wq2; accq[i].w += av[i]*wq3;
                acck[i].x += av[i]*wk0; acck[i].y += av[i]*wk1;
                acck[i].z += av[i]*wk2; acck[i].w += av[i]*wk3;
            }
        }
        __syncthreads();
    }
    float4 bq4 = *(const float4*)&bq[ebase + te * 4];
    float4 bk4 = *(const float4*)&bk[ebase + te * 4];
    #pragma unroll
    for (int i = 0; i < 8; ++i) {
        int n = nbase + tn * 8 + i;
        size_t o = ((size_t)b * Nn + n) * Ee + ebase + te * 4;
        float qa[4] = {accq[i].x + bq4.x, accq[i].y + bq4.y, accq[i].z + bq4.z, accq[i].w + bq4.w};
        float ka[4] = {acck[i].x + bk4.x, acck[i].y + bk4.y, acck[i].z + bk4.z, acck[i].w + bk4.w};
        ushort4 qh, ql, kh, kl;
        bf16split(qa[0], qh.x, ql.x); bf16split(qa[1], qh.y, ql.y);
        bf16split(qa[2], qh.z, ql.z); bf16split(qa[3], qh.w, ql.w);
        bf16split(ka[0], kh.x, kl.x); bf16split(ka[1], kh.y, kl.y);
        bf16split(ka[2], kh.z, kl.z); bf16split(ka[3], kh.w, kl.w);
        *(ushort4*)&g_Qh[o] = qh; *(ushort4*)&g_Ql[o] = ql;
        *(ushort4*)&g_Kh[o] = kh; *(ushort4*)&g_Kl[o] = kl;
    }
}

// ---------------- K2m: scores via mma.sync + ldmatrix; E->bf16 split; colsum atomics ----------------
__global__ __launch_bounds__(256) void k2m(const int* __restrict__ adj)
{
    __shared__ uint32_t sAh[128 * 12];
    __shared__ uint32_t sAl[128 * 12];
    __shared__ uint32_t sBh[128 * 12];
    __shared__ uint32_t sBl[128 * 12];

    int tid = threadIdx.x;
    int wid = tid / 32, lane = tid % 32;
    int wm = wid >> 1, wn = wid & 1;       // placeholder (overwritten below)
    wm = wid >> 2; wn = wid & 3;
    int g = lane >> 2, q = lane & 3;
    int b = blockIdx.z, mbase = blockIdx.y * 128, nbase = blockIdx.x * 128;

    const uint16_t* pQh = g_Qh + ((size_t)b * Nn + mbase) * Ee;
    const uint16_t* pQl = g_Ql + ((size_t)b * Nn + mbase) * Ee;
    const uint16_t* pKh = g_Kh + ((size_t)b * Nn + nbase) * Ee;
    const uint16_t* pKl = g_Kl + ((size_t)b * Nn + nbase) * Ee;

    uint32_t aAh = smem_u32(sAh), aAl = smem_u32(sAl);
    uint32_t aBh = smem_u32(sBh), aBl = smem_u32(sBl);

    int lrowA = lane & 15;
    int lcolA = (lane & 16) ? 4 : 0;
    int browB = lane & 7;
    int bselB = (lane & 8) ? 4 : 0;
    int bhalfB = (lane & 16) ? 8 : 0;

    float acc[4][4][4];
    #pragma unroll
    for (int i = 0; i < 4; ++i)
        #pragma unroll
        for (int j = 0; j < 4; ++j)
            #pragma unroll
            for (int c = 0; c < 4; ++c) acc[i][j][c] = 0.f;

    #pragma unroll 1
    for (int ks = 0; ks < 16; ++ks) {
        int kbase = ks * 16;
        #pragma unroll
        for (int p = 0; p < 2; ++p) {
            int v = tid + 256 * p;
            int row = v >> 2, qq = v & 3;
            size_t off = (size_t)row * Ee + kbase + qq * 4;
            *(uint2*)&sAh[row*12 + qq*2] = *(const uint2*)(pQh + off);
            *(uint2*)&sAl[row*12 + qq*2] = *(const uint2*)(pQl + off);
            *(uint2*)&sBh[row*12 + qq*2] = *(const uint2*)(pKh + off);
            *(uint2*)&sBl[row*12 + qq*2] = *(const uint2*)(pKl + off);
        }
        __syncthreads();

        uint32_t ah[4][4], al[4][4], bh[4][2], bl[4][2];
        #pragma unroll
        for (int i = 0; i < 4; ++i) {
            uint32_t offA = (uint32_t)(((wm * 64 + i * 16 + lrowA) * 12 + lcolA) * 4);
            ldsm4(ah[i], aAh + offA);
            ldsm4(al[i], aAl + offA);
        }
        #pragma unroll
        for (int jj = 0; jj < 2; ++jj) {
            uint32_t offB = (uint32_t)(((wn * 32 + jj * 16 + bhalfB + browB) * 12 + bselB) * 4);
            uint32_t th[4], tl[4];
            ldsm4(th, aBh + offB);
            ldsm4(tl, aBl + offB);
            bh[2*jj][0] = th[0]; bh[2*jj][1] = th[1]; bh[2*jj+1][0] = th[2]; bh[2*jj+1][1] = th[3];
            bl[2*jj][0] = tl[0]; bl[2*jj][1] = tl[1]; bl[2*jj+1][0] = tl[2]; bl[2*jj+1][1] = tl[3];
        }
        #pragma unroll
        for (int i = 0; i < 4; ++i)
            #pragma unroll
            for (int j = 0; j < 4; ++j) {
                mma16816(acc[i][j], ah[i], bh[j]);
                mma16816(acc[i][j], ah[i], bl[j]);
                mma16816(acc[i][j], al[i], bh[j]);
            }
        __syncthreads();
    }

    // epilogue: mask + exp, bf16 split store, column-sum atomics
    float csum[4][2];
    #pragma unroll
    for (int j = 0; j < 4; ++j) { csum[j][0] = 0.f; csum[j][1] = 0.f; }

    #pragma unroll
    for (int i = 0; i < 4; ++i) {
        #pragma unroll
        for (int half = 0; half < 2; ++half) {
            int r = mbase + wm * 64 + i * 16 + g + half * 8;
            const int* adjrow = adj + (size_t)r * Nn;
            size_t erow = ((size_t)b * Nn + r) * Nn;
            #pragma unroll
            for (int j = 0; j < 4; ++j) {
                int cidx = nbase + wn * 32 + j * 8 + q * 2;
                int2 a2 = *(const int2*)(adjrow + cidx);
                float e0 = (a2.x > 0) ? __expf(acc[i][j][half * 2 + 0]) : 0.f;
                float e1 = (a2.y > 0) ? __expf(acc[i][j][half * 2 + 1]) : 0.f;
                uint16_t h0, l0, h1, l1;
                bf16split(e0, h0, l0);
                bf16split(e1, h1, l1);
                *(uint32_t*)&g_Eh[erow + cidx] = (uint32_t)h0 | ((uint32_t)h1 << 16);
                *(uint32_t*)&g_El[erow + cidx] = (uint32_t)l0 | ((uint32_t)l1 << 16);
                csum[j][0] += e0; csum[j][1] += e1;
            }
        }
    }
    #pragma unroll
    for (int j = 0; j < 4; ++j) {
        int cidx = nbase + wn * 32 + j * 8 + q * 2;
        atomicAdd(&g_cs[b * Nn + cidx],     csum[j][0]);
        atomicAdd(&g_cs[b * Nn + cidx + 1], csum[j][1]);
    }
}

// ---------------- K3: xn = x / colsum -> bf16 hi/lo ----------------
__global__ void k3_xn(const float* __restrict__ x) {
    int idx = blockIdx.x * 256 + threadIdx.x;
    if (idx < Bb * Ss * Nn) {
        int j = idx % Nn;
        int b = idx / (Ss * Nn);
        float v = x[idx] / g_cs[b * Nn + j];
        uint16_t h, l;
        bf16split(v, h, l);
        g_xnh[idx] = h;
        g_xnl[idx] = l;
    }
}

// ---------------- K4m: AGG via mma.sync (E @ xn^T) ----------------
// grid (16 itiles, 16 b), 256 thr, 8 warps; warp = m16(i) x n64(t), K=2048 over j.
__global__ __launch_bounds__(256) void k4m()
{
    __shared__ uint16_t sEh[128 * 40];
    __shared__ uint16_t sEl[128 * 40];
    __shared__ uint16_t sXh[64 * 40];
    __shared__ uint16_t sXl[64 * 40];

    int tid = threadIdx.x;
    int w = tid / 32, lane = tid % 32;
    int b = blockIdx.y, ibase = blockIdx.x * 128;

    const uint16_t* pEh = g_Eh + ((size_t)b * Nn + ibase) * Nn;
    const uint16_t* pEl = g_El + ((size_t)b * Nn + ibase) * Nn;
    const uint16_t* pXh = g_xnh + (size_t)b * Ss * Nn;
    const uint16_t* pXl = g_xnl + (size_t)b * Ss * Nn;

    uint32_t aEh = smem_u32(sEh), aEl = smem_u32(sEl);
    uint32_t aXh = smem_u32(sXh), aXl = smem_u32(sXl);

    int lrowA = lane & 15;
    int lcolA = (lane & 16) ? 16 : 0;   // bytes
    int browB = lane & 7;
    int bselB = (lane & 8) ? 16 : 0;    // bytes
    int bhalfB = (lane & 16) ? 8 : 0;

    float acc[8][4];
    #pragma unroll
    for (int j = 0; j < 8; ++j)
        #pragma unroll
        for (int c = 0; c < 4; ++c) acc[j][c] = 0.f;

    #pragma unroll 1
    for (int jc = 0; jc < 64; ++jc) {
        int j0 = jc * 32;
        {   // E: 128 rows x 32 cols, 32B per (row,half)
            int row = tid >> 1, hf = tid & 1;
            const uint16_t* s = pEh + (size_t)row * Nn + j0 + hf * 16;
            uint16_t* d = sEh + row * 40 + hf * 16;
            *(uint4*)d = *(const uint4*)s;
            *(uint4*)(d + 8) = *(const uint4*)(s + 8);
            s = pEl + (size_t)row * Nn + j0 + hf * 16;
            d = sEl + row * 40 + hf * 16;
            *(uint4*)d = *(const uint4*)s;
            *(uint4*)(d + 8) = *(const uint4*)(s + 8);
        }
        {   // xn: 64 rows x 32 cols, 16B per (row,quarter)
            int row = tid >> 2, q4 = tid & 3;
            *(uint4*)(sXh + row * 40 + q4 * 8) = *(const uint4*)(pXh + (size_t)row * Nn + j0 + q4 * 8);
            *(uint4*)(sXl + row * 40 + q4 * 8) = *(const uint4*)(pXl + (size_t)row * Nn + j0 + q4 * 8);
        }
        __syncthreads();

        #pragma unroll
        for (int s = 0; s < 2; ++s) {
            uint32_t ah[4], al[4];
            uint32_t offA = (uint32_t)((w * 16 + lrowA) * 80 + s * 32 + lcolA);
            ldsm4(ah, aEh + offA);
            ldsm4(al, aEl + offA);
            #pragma unroll
            for (int jj = 0; jj < 4; ++jj) {
                uint32_t offB = (uint32_t)((jj * 16 + bhalfB + browB) * 80 + s * 32 + bselB);
                uint32_t th[4], tl[4];
                ldsm4(th, aXh + offB);
                ldsm4(tl, aXl + offB);
                uint32_t bh0[2] = {th[0], th[1]}, bh1[2] = {th[2], th[3]};
                uint32_t bl0[2] = {tl[0], tl[1]}, bl1[2] = {tl[2], tl[3]};
                mma16816(acc[2*jj],   ah, bh0);
                mma16816(acc[2*jj],   ah, bl0);
                mma16816(acc[2*jj],   al, bh0);
                mma16816(acc[2*jj+1], ah, bh1);
                mma16816(acc[2*jj+1], ah, bl1);
                mma16816(acc[2*jj+1], al, bh1);
            }
        }
        __syncthreads();
    }

    // epilogue: C(row=i, col=t) -> AGG[t][b][i]
    int g = lane >> 2, q = lane & 3;
    int i0 = ibase + w * 16 + g;
    #pragma unroll
    for (int j8 = 0; j8 < 8; ++j8) {
        int t0 = j8 * 8 + q * 2;
        g_AGG[(size_t)t0 * (Bb * Nn) + b * Nn + i0]           = acc[j8][0];
        g_AGG[(size_t)(t0 + 1) * (Bb * Nn) + b * Nn + i0]     = acc[j8][1];
        g_AGG[(size_t)t0 * (Bb * Nn) + b * Nn + i0 + 8]       = acc[j8][2];
        g_AGG[(size_t)(t0 + 1) * (Bb * Nn) + b * Nn + i0 + 8] = acc[j8][3];
    }
}

// ---------------- K5p: persistent recurrence (all 64 steps) ----------------
__global__ __launch_bounds__(256, 2) void k5p(
    const float* __restrict__ bhr, const float* __restrict__ bhz,
    const float* __restrict__ bhn)
{
    int tid = threadIdx.x;
    int bid = blockIdx.x;
    int nblkI = bid & 7;
    int ksI   = (bid >> 3) & 7;
    int gate  = bid >> 6;
    int w = tid / 32, lane = tid % 32;
    int ntbase = nblkI * 32 + w * 4;
    int ksbase = ksI * 16;
    int r = lane >> 2;
    int kp = (lane & 3) * 2;

    int gid = bid * 256 + tid;
    float rb = 0.f, zb = 0.f, nb = 0.f, hloc = 0.f;
    bool own = (gid < Bb * Nn);
    if (own) { int i = gid % Nn; rb = bhr[i]; zb = bhz[i]; nb = bhn[i]; }

    float* Pme = g_part + (size_t)(gate * KS2 + ksI) * (Bb * Nn);
    unsigned target = 0;

    for (int t = 0; t < Ss; ++t) {
        float acc[4][4];
        #pragma unroll
        for (int j = 0; j < 4; ++j)
            #pragma unroll
            for (int c = 0; c < 4; ++c) acc[j][c] = 0.f;

        #pragma unroll 4
        for (int kst = 0; kst < 16; ++kst) {
            int kstep = ksbase + kst;
            int k0 = kstep * 16;
            uint32_t ah[4], al[4];
            ah[0] = __ldcg((const uint32_t*)&g_hh[r * Nn + k0 + kp]);
            ah[1] = __ldcg((const uint32_t*)&g_hh[(r + 8) * Nn + k0 + kp]);
            ah[2] = __ldcg((const uint32_t*)&g_hh[r * Nn + k0 + 8 + kp]);
            ah[3] = __ldcg((const uint32_t*)&g_hh[(r + 8) * Nn + k0 + 8 + kp]);
            al[0] = __ldcg((const uint32_t*)&g_hl[r * Nn + k0 + kp]);
            al[1] = __ldcg((const uint32_t*)&g_hl[(r + 8) * Nn + k0 + kp]);
            al[2] = __ldcg((const uint32_t*)&g_hl[r * Nn + k0 + 8 + kp]);
            al[3] = __ldcg((const uint32_t*)&g_hl[(r + 8) * Nn + k0 + 8 + kp]);
            #pragma unroll
            for (int j = 0; j < 4; ++j) {
                size_t bidx = (((size_t)(gate * 256 + ntbase + j) * 128 + kstep) * 32 + lane) * 2;
                uint2 bh = *(const uint2*)&g_WFh[bidx];
                uint2 bl = *(const uint2*)&g_WFl[bidx];
                mma16816(acc[j], ah, (const uint32_t*)&bh);
                mma16816(acc[j], ah, (const uint32_t*)&bl);
                mma16816(acc[j], al, (const uint32_t*)&bh);
            }
        }
        #pragma unroll
        for (int j = 0; j < 4; ++j) {
            int ncol = (ntbase + j) * 8 + kp;
            *(float2*)&Pme[r * Nn + ncol]       = make_float2(acc[j][0], acc[j][1]);
            *(float2*)&Pme[(r + 8) * Nn + ncol] = make_float2(acc[j][2], acc[j][3]);
        }

        target += NPB;
        __syncthreads();
        if (tid == 0) {
            __threadfence();
            atomicAdd(&g_barcnt, 1u);
            while (*(volatile unsigned*)&g_barcnt < target) __nanosleep(64);
        }
        __syncthreads();

        if (own) {
            float rl = rb, zl = zb, nl = nb;
            #pragma unroll
            for (int p = 0; p < KS2; ++p) {
                rl += __ldcg(&g_part[(size_t)(0 * KS2 + p) * (Bb * Nn) + gid]);
                zl += __ldcg(&g_part[(size_t)(1 * KS2 + p) * (Bb * Nn) + gid]);
                nl += __ldcg(&g_part[(size_t)(2 * KS2 + p) * (Bb * Nn) + gid]);
            }
            float agg = g_AGG[(size_t)t * (Bb * Nn) + gid];
            float rr = 1.f / (1.f + expf(-(agg + rl)));
            float zz = 1.f / (1.f + expf(-(agg + zl)));
            float nn2 = tanhf(agg + rr * nl);
            float hn = (1.f - zz) * nn2 + zz * hloc;
            hloc = hn;
            __nv_bfloat16 hb = __float2bfloat16(hn);
            g_hh[gid] = hb;
            g_hl[gid] = __float2bfloat16(hn - __bfloat162float(hb));
            if (t == Ss - 1) g_h[gid] = hn;
        }

        target += NPB;
        __syncthreads();
        if (tid == 0) {
            __threadfence();
            atomicAdd(&g_barcnt, 1u);
            while (*(volatile unsigned*)&g_barcnt < target) __nanosleep(64);
        }
        __syncthreads();
    }
}

// ---------------- K7: out[b] = h[b,:].Wo + bo ----------------
__global__ void k7_out(const float* __restrict__ Wo, const float* __restrict__ bo,
                       float* __restrict__ out)
{
    __shared__ float red[256];
    int b = blockIdx.x, tid = threadIdx.x;
    float s = 0.f;
    for (int i = tid; i < Nn; i += 256) s += g_h[b * Nn + i] * Wo[i];
    red[tid] = s;
    __syncthreads();
    for (int off = 128; off > 0; off >>= 1) {
        if (tid < off) red[tid] += red[tid + off];
        __syncthreads();
    }
    if (tid == 0) out[b] = red[0] + bo[0];
}

extern "C" void kernel_launch(void* const* d_in, const int* in_sizes, int n_in,
                              void* d_out, int out_size) {
    const float* x   = (const float*)d_in[0];
    const int*   adj = (const int*)  d_in[1];
    const float* Wq  = (const float*)d_in[2];
    const float* bq  = (const float*)d_in[3];
    const float* Wk  = (const float*)d_in[4];
    const float* bk  = (const float*)d_in[5];
    const float* Whr = (const float*)d_in[6];
    const float* bhr = (const float*)d_in[7];
    const float* Whz = (const float*)d_in[8];
    const float* bhz = (const float*)d_in[9];
    const float* Whn = (const float*)d_in[10];
    const float* bhn = (const float*)d_in[11];
    const float* Wo  = (const float*)d_in[12];
    const float* bo  = (const float*)d_in[13];
    float* out = (float*)d_out;

    k0_zero<<<(Bb * Nn + 255) / 256, 256>>>();
    kw_split<<<(3 * Nn * (Nn / 2) + 255) / 256, 256>>>(Whr, Whz, Whn);
    k1_qk<<<dim3(Nn / 128, Ee / 64, Bb), 256>>>(x, Wq, bq, Wk, bk);
    k2m<<<dim3(Nn / 128, Nn / 128, Bb), 256>>>(adj);
    k3_xn<<<(Bb * Ss * Nn + 255) / 256, 256>>>(x);
    k4m<<<dim3(Nn / 128, Bb), 256>>>();
    k5p<<<NPB, 256>>>(bhr, bhz, bhn);
    k7_out<<<Bb, 256>>>(Wo, bo, out);
}

// round 13
// speedup vs baseline: 7.8451x; 1.1139x over previous
#include <cuda_runtime.h>
#include <cuda_bf16.h>
#include <cstdint>

constexpr int Bb = 16, Ss = 64, Nn = 2048, Ee = 256;
constexpr int KS3 = 12;    // k-ranges for recurrence MMA
constexpr int NPB = 288;   // persistent blocks (3 gates x 8 nblk x 12 ks) = 144*2

// ---------------- scratch ----------------
__device__ uint16_t g_Eh[(size_t)Bb * Nn * Nn];
__device__ uint16_t g_El[(size_t)Bb * Nn * Nn];
__device__ float g_cs[Bb * Nn];
__device__ float g_AGG[Ss * Bb * Nn];
__device__ float g_part[3 * KS3 * Bb * Nn];
__device__ float g_h[Bb * Nn];
__device__ uint16_t g_Qh[(size_t)Bb * Nn * Ee];
__device__ uint16_t g_Ql[(size_t)Bb * Nn * Ee];
__device__ uint16_t g_Kh[(size_t)Bb * Nn * Ee];
__device__ uint16_t g_Kl[(size_t)Bb * Nn * Ee];
__device__ uint32_t g_WFh[3u * 256 * 128 * 64];
__device__ uint32_t g_WFl[3u * 256 * 128 * 64];
__device__ __nv_bfloat16 g_hh[Bb * Nn];
__device__ __nv_bfloat16 g_hl[Bb * Nn];
__device__ unsigned g_barcnt;

__device__ __forceinline__ void bf16split(float f, uint16_t& h, uint16_t& l) {
    __nv_bfloat16 hb = __float2bfloat16(f);
    __nv_bfloat16 lb = __float2bfloat16(f - __bfloat162float(hb));
    h = *(uint16_t*)&hb; l = *(uint16_t*)&lb;
}
__device__ __forceinline__ void mma16816(float* c, const uint32_t* a, const uint32_t* bfr) {
    asm volatile(
        "mma.sync.aligned.m16n8k16.row.col.f32.bf16.bf16.f32 "
        "{%0,%1,%2,%3}, {%4,%5,%6,%7}, {%8,%9}, {%0,%1,%2,%3};"
        : "+f"(c[0]), "+f"(c[1]), "+f"(c[2]), "+f"(c[3])
        : "r"(a[0]), "r"(a[1]), "r"(a[2]), "r"(a[3]), "r"(bfr[0]), "r"(bfr[1]));
}
__device__ __forceinline__ uint32_t smem_u32(const void* p) {
    uint32_t a;
    asm("{ .reg .u64 t; cvta.to.shared.u64 t, %1; cvt.u32.u64 %0, t; }" : "=r"(a) : "l"(p));
    return a;
}
__device__ __forceinline__ void ldsm4(uint32_t* d, uint32_t addr) {
    asm volatile("ldmatrix.sync.aligned.m8n8.x4.shared.b16 {%0,%1,%2,%3}, [%4];"
        : "=r"(d[0]), "=r"(d[1]), "=r"(d[2]), "=r"(d[3]) : "r"(addr));
}

// ======== Fused setup kernel: [0,1024)=k1 proj, [1024,1152)=zero, [1152,25728)=W split ========
constexpr int A_K1 = 1024, A_Z = A_K1 + 128, A_W = A_Z + 24576;

__global__ __launch_bounds__(256) void kA(
    const float* __restrict__ x,
    const float* __restrict__ Wq, const float* __restrict__ bq,
    const float* __restrict__ Wk, const float* __restrict__ bk,
    const float* __restrict__ Whr, const float* __restrict__ Whz,
    const float* __restrict__ Whn)
{
    int bid = blockIdx.x;
    int tid = threadIdx.x;

    if (bid >= A_Z) {
        // ---- W gate-weight split into fragment order ----
        long long t = (long long)(bid - A_Z) * 256 + tid;
        int gate = (int)(t / (Nn * (Nn / 2)));
        int rem  = (int)(t % (Nn * (Nn / 2)));
        int n = rem / (Nn / 2);
        int k = (rem % (Nn / 2)) * 2;
        const float* W = (gate == 0) ? Whr : ((gate == 1) ? Whz : Whn);
        float w0 = W[(size_t)n * Nn + k];
        float w1 = W[(size_t)n * Nn + k + 1];
        uint16_t h0, l0, h1, l1;
        bf16split(w0, h0, l0);
        bf16split(w1, h1, l1);
        uint32_t idx = ((((uint32_t)gate * 256 + (n >> 3)) * 128 + (k >> 4)) * 32
                        + ((n & 7) * 4 + ((k & 7) >> 1))) * 2 + ((k & 15) >> 3);
        g_WFh[idx] = (uint32_t)h0 | ((uint32_t)h1 << 16);
        g_WFl[idx] = (uint32_t)l0 | ((uint32_t)l1 << 16);
        return;
    }
    if (bid >= A_K1) {
        // ---- zero cs/h/hh/hl + barrier counter ----
        int idx = (bid - A_K1) * 256 + tid;
        if (idx == 0) g_barcnt = 0u;
        if (idx < Bb * Nn) {
            g_cs[idx] = 0.f; g_h[idx] = 0.f;
            g_hh[idx] = __float2bfloat16(0.f);
            g_hl[idx] = __float2bfloat16(0.f);
        }
        return;
    }

    // ---- Q,K projection -> bf16 hi/lo ----
    __shared__ float As[16][132];
    __shared__ float wqs[64][16];
    __shared__ float wks[64][16];
    int bx = bid & 15, by = (bid >> 4) & 3, bz = bid >> 6;
    int b = bz, nbase = bx * 128, ebase = by * 64;
    int tn = tid % 16, te = tid / 16;

    float4 accq[8], acck[8];
    #pragma unroll
    for (int i = 0; i < 8; ++i) { accq[i] = make_float4(0,0,0,0); acck[i] = make_float4(0,0,0,0); }

    for (int kc = 0; kc < 4; ++kc) {
        int kbase = kc * 16;
        #pragma unroll
        for (int p = 0; p < 2; ++p) {
            int v = tid + 256 * p;
            int k = v / 32, mq = v % 32;
            *(float4*)&As[k][mq * 4] =
                *(const float4*)&x[((size_t)(b * Ss + kbase + k)) * Nn + nbase + mq * 4];
        }
        {
            int e = tid / 4, kq = tid % 4;
            *(float4*)&wqs[e][kq * 4] = *(const float4*)&Wq[(ebase + e) * Ss + kbase + kq * 4];
            *(float4*)&wks[e][kq * 4] = *(const float4*)&Wk[(ebase + e) * Ss + kbase + kq * 4];
        }
        __syncthreads();
        #pragma unroll
        for (int kk = 0; kk < 16; ++kk) {
            float4 alo = *(float4*)&As[kk][tn * 8];
            float4 ahi = *(float4*)&As[kk][tn * 8 + 4];
            float av[8] = {alo.x, alo.y, alo.z, alo.w, ahi.x, ahi.y, ahi.z, ahi.w};
            float wq0 = wqs[te*4+0][kk], wq1 = wqs[te*4+1][kk];
            float wq2 = wqs[te*4+2][kk], wq3 = wqs[te*4+3][kk];
            float wk0 = wks[te*4+0][kk], wk1 = wks[te*4+1][kk];
            float wk2 = wks[te*4+2][kk], wk3 = wks[te*4+3][kk];
            #pragma unroll
            for (int i = 0; i < 8; ++i) {
                accq[i].x += av[i]*wq0; accq[i].y += av[i]*wq1;
                accq[i].z += av[i]*wq2; accq[i].w += av[i]*wq3;
                acck[i].x += av[i]*wk0; acck[i].y += av[i]*wk1;
                acck[i].z += av[i]*wk2; acck[i].w += av[i]*wk3;
            }
        }
        __syncthreads();
    }
    float4 bq4 = *(const float4*)&bq[ebase + te * 4];
    float4 bk4 = *(const float4*)&bk[ebase + te * 4];
    #pragma unroll
    for (int i = 0; i < 8; ++i) {
        int n = nbase + tn * 8 + i;
        size_t o = ((size_t)b * Nn + n) * Ee + ebase + te * 4;
        float qa[4] = {accq[i].x + bq4.x, accq[i].y + bq4.y, accq[i].z + bq4.z, accq[i].w + bq4.w};
        float ka[4] = {acck[i].x + bk4.x, acck[i].y + bk4.y, acck[i].z + bk4.z, acck[i].w + bk4.w};
        ushort4 qh, ql, kh, kl;
        bf16split(qa[0], qh.x, ql.x); bf16split(qa[1], qh.y, ql.y);
        bf16split(qa[2], qh.z, ql.z); bf16split(qa[3], qh.w, ql.w);
        bf16split(ka[0], kh.x, kl.x); bf16split(ka[1], kh.y, kl.y);
        bf16split(ka[2], kh.z, kl.z); bf16split(ka[3], kh.w, kl.w);
        *(ushort4*)&g_Qh[o] = qh; *(ushort4*)&g_Ql[o] = ql;
        *(ushort4*)&g_Kh[o] = kh; *(ushort4*)&g_Kl[o] = kl;
    }
}

// ---------------- K2m: scores via mma.sync + ldmatrix; E->bf16 split; colsum atomics ----------------
__global__ __launch_bounds__(256) void k2m(const int* __restrict__ adj)
{
    __shared__ uint32_t sAh[128 * 12];
    __shared__ uint32_t sAl[128 * 12];
    __shared__ uint32_t sBh[128 * 12];
    __shared__ uint32_t sBl[128 * 12];

    int tid = threadIdx.x;
    int wid = tid / 32, lane = tid % 32;
    int wm = wid >> 2, wn = wid & 3;
    int g = lane >> 2, q = lane & 3;
    int b = blockIdx.z, mbase = blockIdx.y * 128, nbase = blockIdx.x * 128;

    const uint16_t* pQh = g_Qh + ((size_t)b * Nn + mbase) * Ee;
    const uint16_t* pQl = g_Ql + ((size_t)b * Nn + mbase) * Ee;
    const uint16_t* pKh = g_Kh + ((size_t)b * Nn + nbase) * Ee;
    const uint16_t* pKl = g_Kl + ((size_t)b * Nn + nbase) * Ee;

    uint32_t aAh = smem_u32(sAh), aAl = smem_u32(sAl);
    uint32_t aBh = smem_u32(sBh), aBl = smem_u32(sBl);

    int lrowA = lane & 15;
    int lcolA = (lane & 16) ? 4 : 0;
    int browB = lane & 7;
    int bselB = (lane & 8) ? 4 : 0;
    int bhalfB = (lane & 16) ? 8 : 0;

    float acc[4][4][4];
    #pragma unroll
    for (int i = 0; i < 4; ++i)
        #pragma unroll
        for (int j = 0; j < 4; ++j)
            #pragma unroll
            for (int c = 0; c < 4; ++c) acc[i][j][c] = 0.f;

    #pragma unroll 1
    for (int ks = 0; ks < 16; ++ks) {
        int kbase = ks * 16;
        #pragma unroll
        for (int p = 0; p < 2; ++p) {
            int v = tid + 256 * p;
            int row = v >> 2, qq = v & 3;
            size_t off = (size_t)row * Ee + kbase + qq * 4;
            *(uint2*)&sAh[row*12 + qq*2] = *(const uint2*)(pQh + off);
            *(uint2*)&sAl[row*12 + qq*2] = *(const uint2*)(pQl + off);
            *(uint2*)&sBh[row*12 + qq*2] = *(const uint2*)(pKh + off);
            *(uint2*)&sBl[row*12 + qq*2] = *(const uint2*)(pKl + off);
        }
        __syncthreads();

        uint32_t ah[4][4], al[4][4], bh[4][2], bl[4][2];
        #pragma unroll
        for (int i = 0; i < 4; ++i) {
            uint32_t offA = (uint32_t)(((wm * 64 + i * 16 + lrowA) * 12 + lcolA) * 4);
            ldsm4(ah[i], aAh + offA);
            ldsm4(al[i], aAl + offA);
        }
        #pragma unroll
        for (int jj = 0; jj < 2; ++jj) {
            uint32_t offB = (uint32_t)(((wn * 32 + jj * 16 + bhalfB + browB) * 12 + bselB) * 4);
            uint32_t th[4], tl[4];
            ldsm4(th, aBh + offB);
            ldsm4(tl, aBl + offB);
            bh[2*jj][0] = th[0]; bh[2*jj][1] = th[1]; bh[2*jj+1][0] = th[2]; bh[2*jj+1][1] = th[3];
            bl[2*jj][0] = tl[0]; bl[2*jj][1] = tl[1]; bl[2*jj+1][0] = tl[2]; bl[2*jj+1][1] = tl[3];
        }
        #pragma unroll
        for (int i = 0; i < 4; ++i)
            #pragma unroll
            for (int j = 0; j < 4; ++j) {
                mma16816(acc[i][j], ah[i], bh[j]);
                mma16816(acc[i][j], ah[i], bl[j]);
                mma16816(acc[i][j], al[i], bh[j]);
            }
        __syncthreads();
    }

    float csum[4][2];
    #pragma unroll
    for (int j = 0; j < 4; ++j) { csum[j][0] = 0.f; csum[j][1] = 0.f; }

    #pragma unroll
    for (int i = 0; i < 4; ++i) {
        #pragma unroll
        for (int half = 0; half < 2; ++half) {
            int r = mbase + wm * 64 + i * 16 + g + half * 8;
            const int* adjrow = adj + (size_t)r * Nn;
            size_t erow = ((size_t)b * Nn + r) * Nn;
            #pragma unroll
            for (int j = 0; j < 4; ++j) {
                int cidx = nbase + wn * 32 + j * 8 + q * 2;
                int2 a2 = *(const int2*)(adjrow + cidx);
                float e0 = (a2.x > 0) ? __expf(acc[i][j][half * 2 + 0]) : 0.f;
                float e1 = (a2.y > 0) ? __expf(acc[i][j][half * 2 + 1]) : 0.f;
                uint16_t h0, l0, h1, l1;
                bf16split(e0, h0, l0);
                bf16split(e1, h1, l1);
                *(uint32_t*)&g_Eh[erow + cidx] = (uint32_t)h0 | ((uint32_t)h1 << 16);
                *(uint32_t*)&g_El[erow + cidx] = (uint32_t)l0 | ((uint32_t)l1 << 16);
                csum[j][0] += e0; csum[j][1] += e1;
            }
        }
    }
    #pragma unroll
    for (int j = 0; j < 4; ++j) {
        int cidx = nbase + wn * 32 + j * 8 + q * 2;
        atomicAdd(&g_cs[b * Nn + cidx],     csum[j][0]);
        atomicAdd(&g_cs[b * Nn + cidx + 1], csum[j][1]);
    }
}

// ---------------- K4m: AGG via mma.sync (E @ xn^T), xn computed inline ----------------
__global__ __launch_bounds__(256) void k4m(const float* __restrict__ x)
{
    __shared__ uint16_t sEh[128 * 40];
    __shared__ uint16_t sEl[128 * 40];
    __shared__ uint16_t sXh[64 * 40];
    __shared__ uint16_t sXl[64 * 40];
    __shared__ float rcs[Nn];

    int tid = threadIdx.x;
    int w = tid / 32, lane = tid % 32;
    int b = blockIdx.y, ibase = blockIdx.x * 128;

    // reciprocal colsum table (IEEE div, once per block)
    for (int j = tid; j < Nn; j += 256) rcs[j] = 1.0f / g_cs[b * Nn + j];
    __syncthreads();

    const uint16_t* pEh = g_Eh + ((size_t)b * Nn + ibase) * Nn;
    const uint16_t* pEl = g_El + ((size_t)b * Nn + ibase) * Nn;
    const float* xb = x + (size_t)b * Ss * Nn;

    uint32_t aEh = smem_u32(sEh), aEl = smem_u32(sEl);
    uint32_t aXh = smem_u32(sXh), aXl = smem_u32(sXl);

    int lrowA = lane & 15;
    int lcolA = (lane & 16) ? 16 : 0;
    int browB = lane & 7;
    int bselB = (lane & 8) ? 16 : 0;
    int bhalfB = (lane & 16) ? 8 : 0;

    float acc[8][4];
    #pragma unroll
    for (int j = 0; j < 8; ++j)
        #pragma unroll
        for (int c = 0; c < 4; ++c) acc[j][c] = 0.f;

    #pragma unroll 1
    for (int jc = 0; jc < 64; ++jc) {
        int j0 = jc * 32;
        {   // E tiles
            int row = tid >> 1, hf = tid & 1;
            const uint16_t* s = pEh + (size_t)row * Nn + j0 + hf * 16;
            uint16_t* d = sEh + row * 40 + hf * 16;
            *(uint4*)d = *(const uint4*)s;
            *(uint4*)(d + 8) = *(const uint4*)(s + 8);
            s = pEl + (size_t)row * Nn + j0 + hf * 16;
            d = sEl + row * 40 + hf * 16;
            *(uint4*)d = *(const uint4*)s;
            *(uint4*)(d + 8) = *(const uint4*)(s + 8);
        }
        {   // xn inline: load x f32, scale by rcs, split to bf16 hi/lo
            int row = tid >> 2, q4 = tid & 3;
            const float* xp = xb + (size_t)row * Nn + j0 + q4 * 8;
            float4 v0 = *(const float4*)xp;
            float4 v1 = *(const float4*)(xp + 4);
            int jb = j0 + q4 * 8;
            float vv[8] = {v0.x * rcs[jb], v0.y * rcs[jb+1], v0.z * rcs[jb+2], v0.w * rcs[jb+3],
                           v1.x * rcs[jb+4], v1.y * rcs[jb+5], v1.z * rcs[jb+6], v1.w * rcs[jb+7]};
            uint16_t hh[8], ll[8];
            #pragma unroll
            for (int e = 0; e < 8; ++e) bf16split(vv[e], hh[e], ll[e]);
            ushort4 ph0 = {hh[0], hh[1], hh[2], hh[3]}, ph1 = {hh[4], hh[5], hh[6], hh[7]};
            ushort4 pl0 = {ll[0], ll[1], ll[2], ll[3]}, pl1 = {ll[4], ll[5], ll[6], ll[7]};
            uint16_t* d = sXh + row * 40 + q4 * 8;
            *(ushort4*)d = ph0; *(ushort4*)(d + 4) = ph1;
            d = sXl + row * 40 + q4 * 8;
            *(ushort4*)d = pl0; *(ushort4*)(d + 4) = pl1;
        }
        __syncthreads();

        #pragma unroll
        for (int s = 0; s < 2; ++s) {
            uint32_t ah[4], al[4];
            uint32_t offA = (uint32_t)((w * 16 + lrowA) * 80 + s * 32 + lcolA);
            ldsm4(ah, aEh + offA);
            ldsm4(al, aEl + offA);
            #pragma unroll
            for (int jj = 0; jj < 4; ++jj) {
                uint32_t offB = (uint32_t)((jj * 16 + bhalfB + browB) * 80 + s * 32 + bselB);
                uint32_t th[4], tl[4];
                ldsm4(th, aXh + offB);
                ldsm4(tl, aXl + offB);
                uint32_t bh0[2] = {th[0], th[1]}, bh1[2] = {th[2], th[3]};
                uint32_t bl0[2] = {tl[0], tl[1]}, bl1[2] = {tl[2], tl[3]};
                mma16816(acc[2*jj],   ah, bh0);
                mma16816(acc[2*jj],   ah, bl0);
                mma16816(acc[2*jj],   al, bh0);
                mma16816(acc[2*jj+1], ah, bh1);
                mma16816(acc[2*jj+1], ah, bl1);
                mma16816(acc[2*jj+1], al, bh1);
            }
        }
        __syncthreads();
    }

    int g = lane >> 2, q = lane & 3;
    int i0 = ibase + w * 16 + g;
    #pragma unroll
    for (int j8 = 0; j8 < 8; ++j8) {
        int t0 = j8 * 8 + q * 2;
        g_AGG[(size_t)t0 * (Bb * Nn) + b * Nn + i0]           = acc[j8][0];
        g_AGG[(size_t)(t0 + 1) * (Bb * Nn) + b * Nn + i0]     = acc[j8][1];
        g_AGG[(size_t)t0 * (Bb * Nn) + b * Nn + i0 + 8]       = acc[j8][2];
        g_AGG[(size_t)(t0 + 1) * (Bb * Nn) + b * Nn + i0 + 8] = acc[j8][3];
    }
}

// ---------------- K5p: persistent recurrence (all 64 steps), 288 balanced blocks ----------------
__device__ __forceinline__ void load_h(int kstep, int r, int kp, uint32_t* ah, uint32_t* al) {
    int k0 = kstep * 16;
    ah[0] = __ldcg((const uint32_t*)&g_hh[r * Nn + k0 + kp]);
    ah[1] = __ldcg((const uint32_t*)&g_hh[(r + 8) * Nn + k0 + kp]);
    ah[2] = __ldcg((const uint32_t*)&g_hh[r * Nn + k0 + 8 + kp]);
    ah[3] = __ldcg((const uint32_t*)&g_hh[(r + 8) * Nn + k0 + 8 + kp]);
    al[0] = __ldcg((const uint32_t*)&g_hl[r * Nn + k0 + kp]);
    al[1] = __ldcg((const uint32_t*)&g_hl[(r + 8) * Nn + k0 + kp]);
    al[2] = __ldcg((const uint32_t*)&g_hl[r * Nn + k0 + 8 + kp]);
    al[3] = __ldcg((const uint32_t*)&g_hl[(r + 8) * Nn + k0 + 8 + kp]);
}

__global__ __launch_bounds__(256, 2) void k5p(
    const float* __restrict__ bhr, const float* __restrict__ bhz,
    const float* __restrict__ bhn)
{
    int tid = threadIdx.x;
    int bid = blockIdx.x;
    int nblkI = bid & 7;
    int ksI   = (bid >> 3) % KS3;
    int gate  = bid / (8 * KS3);
    int w = tid / 32, lane = tid % 32;
    int ntbase = nblkI * 32 + w * 4;
    int kb = (ksI * 128) / KS3;
    int ke = ((ksI + 1) * 128) / KS3;
    int r = lane >> 2;
    int kp = (lane & 3) * 2;

    int gid = bid * 256 + tid;
    float rb = 0.f, zb = 0.f, nb = 0.f, hloc = 0.f;
    bool own = (gid < Bb * Nn);
    if (own) { int i = gid % Nn; rb = bhr[i]; zb = bhz[i]; nb = bhn[i]; }

    float* Pme = g_part + (size_t)(gate * KS3 + ksI) * (Bb * Nn);
    unsigned target = 0;

    for (int t = 0; t < Ss; ++t) {
        float agg = own ? g_AGG[(size_t)t * (Bb * Nn) + gid] : 0.f;   // prefetch

        float acc[4][4];
        #pragma unroll
        for (int j = 0; j < 4; ++j)
            #pragma unroll
            for (int c = 0; c < 4; ++c) acc[j][c] = 0.f;

        uint32_t ah[4], al[4], ahn[4], aln[4];
        load_h(kb, r, kp, ah, al);
        #pragma unroll 2
        for (int kstep = kb; kstep < ke; ++kstep) {
            if (kstep + 1 < ke) load_h(kstep + 1, r, kp, ahn, aln);
            #pragma unroll
            for (int j = 0; j < 4; ++j) {
                size_t bidx = (((size_t)(gate * 256 + ntbase + j) * 128 + kstep) * 32 + lane) * 2;
                uint2 bh = *(const uint2*)&g_WFh[bidx];
                uint2 bl = *(const uint2*)&g_WFl[bidx];
                mma16816(acc[j], ah, (const uint32_t*)&bh);
                mma16816(acc[j], ah, (const uint32_t*)&bl);
                mma16816(acc[j], al, (const uint32_t*)&bh);
            }
            #pragma unroll
            for (int u = 0; u < 4; ++u) { ah[u] = ahn[u]; al[u] = aln[u]; }
        }
        #pragma unroll
        for (int j = 0; j < 4; ++j) {
            int ncol = (ntbase + j) * 8 + kp;
            *(float2*)&Pme[r * Nn + ncol]       = make_float2(acc[j][0], acc[j][1]);
            *(float2*)&Pme[(r + 8) * Nn + ncol] = make_float2(acc[j][2], acc[j][3]);
        }

        target += NPB;
        __syncthreads();
        if (tid == 0) {
            __threadfence();
            atomicAdd(&g_barcnt, 1u);
            while (*(volatile unsigned*)&g_barcnt < target) __nanosleep(64);
        }
        __syncthreads();

        if (own) {
            float rl = rb, zl = zb, nl = nb;
            #pragma unroll
            for (int p = 0; p < KS3; ++p) {
                rl += __ldcg(&g_part[(size_t)(0 * KS3 + p) * (Bb * Nn) + gid]);
                zl += __ldcg(&g_part[(size_t)(1 * KS3 + p) * (Bb * Nn) + gid]);
                nl += __ldcg(&g_part[(size_t)(2 * KS3 + p) * (Bb * Nn) + gid]);
            }
            float rr = 1.f / (1.f + expf(-(agg + rl)));
            float zz = 1.f / (1.f + expf(-(agg + zl)));
            float nn2 = tanhf(agg + rr * nl);
            float hn = (1.f - zz) * nn2 + zz * hloc;
            hloc = hn;
            __nv_bfloat16 hb = __float2bfloat16(hn);
            g_hh[gid] = hb;
            g_hl[gid] = __float2bfloat16(hn - __bfloat162float(hb));
            if (t == Ss - 1) g_h[gid] = hn;
        }

        target += NPB;
        __syncthreads();
        if (tid == 0) {
            __threadfence();
            atomicAdd(&g_barcnt, 1u);
            while (*(volatile unsigned*)&g_barcnt < target) __nanosleep(64);
        }
        __syncthreads();
    }
}

// ---------------- K7: out[b] = h[b,:].Wo + bo ----------------
__global__ void k7_out(const float* __restrict__ Wo, const float* __restrict__ bo,
                       float* __restrict__ out)
{
    __shared__ float red[256];
    int b = blockIdx.x, tid = threadIdx.x;
    float s = 0.f;
    for (int i = tid; i < Nn; i += 256) s += g_h[b * Nn + i] * Wo[i];
    red[tid] = s;
    __syncthreads();
    for (int off = 128; off > 0; off >>= 1) {
        if (tid < off) red[tid] += red[tid + off];
        __syncthreads();
    }
    if (tid == 0) out[b] = red[0] + bo[0];
}

extern "C" void kernel_launch(void* const* d_in, const int* in_sizes, int n_in,
                              void* d_out, int out_size) {
    const float* x   = (const float*)d_in[0];
    const int*   adj = (const int*)  d_in[1];
    const float* Wq  = (const float*)d_in[2];
    const float* bq  = (const float*)d_in[3];
    const float* Wk  = (const float*)d_in[4];
    const float* bk  = (const float*)d_in[5];
    const float* Whr = (const float*)d_in[6];
    const float* bhr = (const float*)d_in[7];
    const float* Whz = (const float*)d_in[8];
    const float* bhz = (const float*)d_in[9];
    const float* Whn = (const float*)d_in[10];
    const float* bhn = (const float*)d_in[11];
    const float* Wo  = (const float*)d_in[12];
    const float* bo  = (const float*)d_in[13];
    float* out = (float*)d_out;

    kA<<<A_W, 256>>>(x, Wq, bq, Wk, bk, Whr, Whz, Whn);
    k2m<<<dim3(Nn / 128, Nn / 128, Bb), 256>>>(adj);
    k4m<<<dim3(Nn / 128, Bb), 256>>>(x);
    k5p<<<NPB, 256>>>(bhr, bhz, bhn);
    k7_out<<<Bb, 256>>>(Wo, bo, out);
}

// round 14
// speedup vs baseline: 8.1368x; 1.0372x over previous
#include <cuda_runtime.h>
#include <cuda_bf16.h>
#include <cstdint>

constexpr int Bb = 16, Ss = 64, Nn = 2048, Ee = 256;
constexpr int KS3 = 12;    // k-ranges for recurrence MMA
constexpr int NPB = 288;   // persistent blocks (3 gates x 8 nblk x 12 ks) = 144*2

// ---------------- scratch ----------------
__device__ uint16_t g_Eh[(size_t)Bb * Nn * Nn];
__device__ uint16_t g_El[(size_t)Bb * Nn * Nn];
__device__ float g_cs[Bb * Nn];
__device__ float g_AGG[Ss * Bb * Nn];
__device__ float g_part[3 * KS3 * Bb * Nn];
__device__ float g_h[Bb * Nn];
__device__ uint16_t g_Qh[(size_t)Bb * Nn * Ee];
__device__ uint16_t g_Ql[(size_t)Bb * Nn * Ee];
__device__ uint16_t g_Kh[(size_t)Bb * Nn * Ee];
__device__ uint16_t g_Kl[(size_t)Bb * Nn * Ee];
// W gate weights, fragment order, hi/lo interleaved per lane:
// [gate][ntile(256)][kstep(128)][lane(32)] -> uint4 {hi_reg0, hi_reg1, lo_reg0, lo_reg1}
__device__ uint4 g_WF4[3u * 256 * 128 * 32];
__device__ __nv_bfloat16 g_hh[Bb * Nn];
__device__ __nv_bfloat16 g_hl[Bb * Nn];
__device__ unsigned g_barcnt;

__device__ __forceinline__ void bf16split(float f, uint16_t& h, uint16_t& l) {
    __nv_bfloat16 hb = __float2bfloat16(f);
    __nv_bfloat16 lb = __float2bfloat16(f - __bfloat162float(hb));
    h = *(uint16_t*)&hb; l = *(uint16_t*)&lb;
}
__device__ __forceinline__ void mma16816(float* c, const uint32_t* a, const uint32_t* bfr) {
    asm volatile(
        "mma.sync.aligned.m16n8k16.row.col.f32.bf16.bf16.f32 "
        "{%0,%1,%2,%3}, {%4,%5,%6,%7}, {%8,%9}, {%0,%1,%2,%3};"
        : "+f"(c[0]), "+f"(c[1]), "+f"(c[2]), "+f"(c[3])
        : "r"(a[0]), "r"(a[1]), "r"(a[2]), "r"(a[3]), "r"(bfr[0]), "r"(bfr[1]));
}
__device__ __forceinline__ uint32_t smem_u32(const void* p) {
    uint32_t a;
    asm("{ .reg .u64 t; cvta.to.shared.u64 t, %1; cvt.u32.u64 %0, t; }" : "=r"(a) : "l"(p));
    return a;
}
__device__ __forceinline__ void ldsm4(uint32_t* d, uint32_t addr) {
    asm volatile("ldmatrix.sync.aligned.m8n8.x4.shared.b16 {%0,%1,%2,%3}, [%4];"
        : "=r"(d[0]), "=r"(d[1]), "=r"(d[2]), "=r"(d[3]) : "r"(addr));
}

// ======== Fused setup kernel: [0,1024)=k1 proj, [1024,1152)=zero, [1152,+12288)=W split ========
constexpr int A_K1 = 1024, A_Z = A_K1 + 128, A_W = A_Z + 12288;

__global__ __launch_bounds__(256) void kA(
    const float* __restrict__ x,
    const float* __restrict__ Wq, const float* __restrict__ bq,
    const float* __restrict__ Wk, const float* __restrict__ bk,
    const float* __restrict__ Whr, const float* __restrict__ Whz,
    const float* __restrict__ Whn)
{
    int bid = blockIdx.x;
    int tid = threadIdx.x;

    if (bid >= A_Z) {
        // ---- W gate-weight split into interleaved uint4 fragment order ----
        long long t = (long long)(bid - A_Z) * 256 + tid;   // over 3*2048*512
        int gate = (int)(t / (Nn * 512));
        int rem  = (int)(t % (Nn * 512));
        int n = rem / 512;
        int s = rem % 512;
        int kstep = s >> 2, q = s & 3;
        int k0 = kstep * 16 + q * 2;
        const float* W = (gate == 0) ? Whr : ((gate == 1) ? Whz : Whn);
        float w0 = W[(size_t)n * Nn + k0];
        float w1 = W[(size_t)n * Nn + k0 + 1];
        float w2 = W[(size_t)n * Nn + k0 + 8];
        float w3 = W[(size_t)n * Nn + k0 + 9];
        uint16_t h0, l0, h1, l1, h2, l2, h3, l3;
        bf16split(w0, h0, l0); bf16split(w1, h1, l1);
        bf16split(w2, h2, l2); bf16split(w3, h3, l3);
        uint4 v;
        v.x = (uint32_t)h0 | ((uint32_t)h1 << 16);   // hi reg0
        v.y = (uint32_t)h2 | ((uint32_t)h3 << 16);   // hi reg1
        v.z = (uint32_t)l0 | ((uint32_t)l1 << 16);   // lo reg0
        v.w = (uint32_t)l2 | ((uint32_t)l3 << 16);   // lo reg1
        int lane = (n & 7) * 4 + q;
        uint32_t idx = (((uint32_t)gate * 256 + (n >> 3)) * 128 + kstep) * 32 + lane;
        g_WF4[idx] = v;
        return;
    }
    if (bid >= A_K1) {
        int idx = (bid - A_K1) * 256 + tid;
        if (idx == 0) g_barcnt = 0u;
        if (idx < Bb * Nn) {
            g_cs[idx] = 0.f; g_h[idx] = 0.f;
            g_hh[idx] = __float2bfloat16(0.f);
            g_hl[idx] = __float2bfloat16(0.f);
        }
        return;
    }

    // ---- Q,K projection -> bf16 hi/lo ----
    __shared__ float As[16][132];
    __shared__ float wqs[64][16];
    __shared__ float wks[64][16];
    int bx = bid & 15, by = (bid >> 4) & 3, bz = bid >> 6;
    int b = bz, nbase = bx * 128, ebase = by * 64;
    int tn = tid % 16, te = tid / 16;

    float4 accq[8], acck[8];
    #pragma unroll
    for (int i = 0; i < 8; ++i) { accq[i] = make_float4(0,0,0,0); acck[i] = make_float4(0,0,0,0); }

    for (int kc = 0; kc < 4; ++kc) {
        int kbase = kc * 16;
        #pragma unroll
        for (int p = 0; p < 2; ++p) {
            int v = tid + 256 * p;
            int k = v / 32, mq = v % 32;
            *(float4*)&As[k][mq * 4] =
                *(const float4*)&x[((size_t)(b * Ss + kbase + k)) * Nn + nbase + mq * 4];
        }
        {
            int e = tid / 4, kq = tid % 4;
            *(float4*)&wqs[e][kq * 4] = *(const float4*)&Wq[(ebase + e) * Ss + kbase + kq * 4];
            *(float4*)&wks[e][kq * 4] = *(const float4*)&Wk[(ebase + e) * Ss + kbase + kq * 4];
        }
        __syncthreads();
        #pragma unroll
        for (int kk = 0; kk < 16; ++kk) {
            float4 alo = *(float4*)&As[kk][tn * 8];
            float4 ahi = *(float4*)&As[kk][tn * 8 + 4];
            float av[8] = {alo.x, alo.y, alo.z, alo.w, ahi.x, ahi.y, ahi.z, ahi.w};
            float wq0 = wqs[te*4+0][kk], wq1 = wqs[te*4+1][kk];
            float wq2 = wqs[te*4+2][kk], wq3 = wqs[te*4+3][kk];
            float wk0 = wks[te*4+0][kk], wk1 = wks[te*4+1][kk];
            float wk2 = wks[te*4+2][kk], wk3 = wks[te*4+3][kk];
            #pragma unroll
            for (int i = 0; i < 8; ++i) {
                accq[i].x += av[i]*wq0; accq[i].y += av[i]*wq1;
                accq[i].z += av[i]*wq2; accq[i].w += av[i]*wq3;
                acck[i].x += av[i]*wk0; acck[i].y += av[i]*wk1;
                acck[i].z += av[i]*wk2; acck[i].w += av[i]*wk3;
            }
        }
        __syncthreads();
    }
    float4 bq4 = *(const float4*)&bq[ebase + te * 4];
    float4 bk4 = *(const float4*)&bk[ebase + te * 4];
    #pragma unroll
    for (int i = 0; i < 8; ++i) {
        int n = nbase + tn * 8 + i;
        size_t o = ((size_t)b * Nn + n) * Ee + ebase + te * 4;
        float qa[4] = {accq[i].x + bq4.x, accq[i].y + bq4.y, accq[i].z + bq4.z, accq[i].w + bq4.w};
        float ka[4] = {acck[i].x + bk4.x, acck[i].y + bk4.y, acck[i].z + bk4.z, acck[i].w + bk4.w};
        ushort4 qh, ql, kh, kl;
        bf16split(qa[0], qh.x, ql.x); bf16split(qa[1], qh.y, ql.y);
        bf16split(qa[2], qh.z, ql.z); bf16split(qa[3], qh.w, ql.w);
        bf16split(ka[0], kh.x, kl.x); bf16split(ka[1], kh.y, kl.y);
        bf16split(ka[2], kh.z, kl.z); bf16split(ka[3], kh.w, kl.w);
        *(ushort4*)&g_Qh[o] = qh; *(ushort4*)&g_Ql[o] = ql;
        *(ushort4*)&g_Kh[o] = kh; *(ushort4*)&g_Kl[o] = kl;
    }
}

// ---------------- K2m: scores via mma.sync + ldmatrix; E->bf16 split; colsum atomics ----------------
__global__ __launch_bounds__(256) void k2m(const int* __restrict__ adj)
{
    __shared__ uint32_t sAh[128 * 12];
    __shared__ uint32_t sAl[128 * 12];
    __shared__ uint32_t sBh[128 * 12];
    __shared__ uint32_t sBl[128 * 12];

    int tid = threadIdx.x;
    int wid = tid / 32, lane = tid % 32;
    int wm = wid >> 2, wn = wid & 3;
    int g = lane >> 2, q = lane & 3;
    int b = blockIdx.z, mbase = blockIdx.y * 128, nbase = blockIdx.x * 128;

    const uint16_t* pQh = g_Qh + ((size_t)b * Nn + mbase) * Ee;
    const uint16_t* pQl = g_Ql + ((size_t)b * Nn + mbase) * Ee;
    const uint16_t* pKh = g_Kh + ((size_t)b * Nn + nbase) * Ee;
    const uint16_t* pKl = g_Kl + ((size_t)b * Nn + nbase) * Ee;

    uint32_t aAh = smem_u32(sAh), aAl = smem_u32(sAl);
    uint32_t aBh = smem_u32(sBh), aBl = smem_u32(sBl);

    int lrowA = lane & 15;
    int lcolA = (lane & 16) ? 4 : 0;
    int browB = lane & 7;
    int bselB = (lane & 8) ? 4 : 0;
    int bhalfB = (lane & 16) ? 8 : 0;

    float acc[4][4][4];
    #pragma unroll
    for (int i = 0; i < 4; ++i)
        #pragma unroll
        for (int j = 0; j < 4; ++j)
            #pragma unroll
            for (int c = 0; c < 4; ++c) acc[i][j][c] = 0.f;

    #pragma unroll 1
    for (int ks = 0; ks < 16; ++ks) {
        int kbase = ks * 16;
        #pragma unroll
        for (int p = 0; p < 2; ++p) {
            int v = tid + 256 * p;
            int row = v >> 2, qq = v & 3;
            size_t off = (size_t)row * Ee + kbase + qq * 4;
            *(uint2*)&sAh[row*12 + qq*2] = *(const uint2*)(pQh + off);
            *(uint2*)&sAl[row*12 + qq*2] = *(const uint2*)(pQl + off);
            *(uint2*)&sBh[row*12 + qq*2] = *(const uint2*)(pKh + off);
            *(uint2*)&sBl[row*12 + qq*2] = *(const uint2*)(pKl + off);
        }
        __syncthreads();

        uint32_t ah[4][4], al[4][4], bh[4][2], bl[4][2];
        #pragma unroll
        for (int i = 0; i < 4; ++i) {
            uint32_t offA = (uint32_t)(((wm * 64 + i * 16 + lrowA) * 12 + lcolA) * 4);
            ldsm4(ah[i], aAh + offA);
            ldsm4(al[i], aAl + offA);
        }
        #pragma unroll
        for (int jj = 0; jj < 2; ++jj) {
            uint32_t offB = (uint32_t)(((wn * 32 + jj * 16 + bhalfB + browB) * 12 + bselB) * 4);
            uint32_t th[4], tl[4];
            ldsm4(th, aBh + offB);
            ldsm4(tl, aBl + offB);
            bh[2*jj][0] = th[0]; bh[2*jj][1] = th[1]; bh[2*jj+1][0] = th[2]; bh[2*jj+1][1] = th[3];
            bl[2*jj][0] = tl[0]; bl[2*jj][1] = tl[1]; bl[2*jj+1][0] = tl[2]; bl[2*jj+1][1] = tl[3];
        }
        #pragma unroll
        for (int i = 0; i < 4; ++i)
            #pragma unroll
            for (int j = 0; j < 4; ++j) {
                mma16816(acc[i][j], ah[i], bh[j]);
                mma16816(acc[i][j], ah[i], bl[j]);
                mma16816(acc[i][j], al[i], bh[j]);
            }
        __syncthreads();
    }

    float csum[4][2];
    #pragma unroll
    for (int j = 0; j < 4; ++j) { csum[j][0] = 0.f; csum[j][1] = 0.f; }

    #pragma unroll
    for (int i = 0; i < 4; ++i) {
        #pragma unroll
        for (int half = 0; half < 2; ++half) {
            int r = mbase + wm * 64 + i * 16 + g + half * 8;
            const int* adjrow = adj + (size_t)r * Nn;
            size_t erow = ((size_t)b * Nn + r) * Nn;
            #pragma unroll
            for (int j = 0; j < 4; ++j) {
                int cidx = nbase + wn * 32 + j * 8 + q * 2;
                int2 a2 = *(const int2*)(adjrow + cidx);
                float e0 = (a2.x > 0) ? __expf(acc[i][j][half * 2 + 0]) : 0.f;
                float e1 = (a2.y > 0) ? __expf(acc[i][j][half * 2 + 1]) : 0.f;
                uint16_t h0, l0, h1, l1;
                bf16split(e0, h0, l0);
                bf16split(e1, h1, l1);
                *(uint32_t*)&g_Eh[erow + cidx] = (uint32_t)h0 | ((uint32_t)h1 << 16);
                *(uint32_t*)&g_El[erow + cidx] = (uint32_t)l0 | ((uint32_t)l1 << 16);
                csum[j][0] += e0; csum[j][1] += e1;
            }
        }
    }
    #pragma unroll
    for (int j = 0; j < 4; ++j) {
        int cidx = nbase + wn * 32 + j * 8 + q * 2;
        atomicAdd(&g_cs[b * Nn + cidx],     csum[j][0]);
        atomicAdd(&g_cs[b * Nn + cidx + 1], csum[j][1]);
    }
}

// ---------------- K4m: AGG via mma.sync (E @ xn^T), xn computed inline ----------------
__global__ __launch_bounds__(256) void k4m(const float* __restrict__ x)
{
    __shared__ uint16_t sEh[128 * 40];
    __shared__ uint16_t sEl[128 * 40];
    __shared__ uint16_t sXh[64 * 40];
    __shared__ uint16_t sXl[64 * 40];
    __shared__ float rcs[Nn];

    int tid = threadIdx.x;
    int w = tid / 32, lane = tid % 32;
    int b = blockIdx.y, ibase = blockIdx.x * 128;

    for (int j = tid; j < Nn; j += 256) rcs[j] = 1.0f / g_cs[b * Nn + j];
    __syncthreads();

    const uint16_t* pEh = g_Eh + ((size_t)b * Nn + ibase) * Nn;
    const uint16_t* pEl = g_El + ((size_t)b * Nn + ibase) * Nn;
    const float* xb = x + (size_t)b * Ss * Nn;

    uint32_t aEh = smem_u32(sEh), aEl = smem_u32(sEl);
    uint32_t aXh = smem_u32(sXh), aXl = smem_u32(sXl);

    int lrowA = lane & 15;
    int lcolA = (lane & 16) ? 16 : 0;
    int browB = lane & 7;
    int bselB = (lane & 8) ? 16 : 0;
    int bhalfB = (lane & 16) ? 8 : 0;

    float acc[8][4];
    #pragma unroll
    for (int j = 0; j < 8; ++j)
        #pragma unroll
        for (int c = 0; c < 4; ++c) acc[j][c] = 0.f;

    #pragma unroll 1
    for (int jc = 0; jc < 64; ++jc) {
        int j0 = jc * 32;
        {
            int row = tid >> 1, hf = tid & 1;
            const uint16_t* s = pEh + (size_t)row * Nn + j0 + hf * 16;
            uint16_t* d = sEh + row * 40 + hf * 16;
            *(uint4*)d = *(const uint4*)s;
            *(uint4*)(d + 8) = *(const uint4*)(s + 8);
            s = pEl + (size_t)row * Nn + j0 + hf * 16;
            d = sEl + row * 40 + hf * 16;
            *(uint4*)d = *(const uint4*)s;
            *(uint4*)(d + 8) = *(const uint4*)(s + 8);
        }
        {
            int row = tid >> 2, q4 = tid & 3;
            const float* xp = xb + (size_t)row * Nn + j0 + q4 * 8;
            float4 v0 = *(const float4*)xp;
            float4 v1 = *(const float4*)(xp + 4);
            int jb = j0 + q4 * 8;
            float vv[8] = {v0.x * rcs[jb], v0.y * rcs[jb+1], v0.z * rcs[jb+2], v0.w * rcs[jb+3],
                           v1.x * rcs[jb+4], v1.y * rcs[jb+5], v1.z * rcs[jb+6], v1.w * rcs[jb+7]};
            uint16_t hh[8], ll[8];
            #pragma unroll
            for (int e = 0; e < 8; ++e) bf16split(vv[e], hh[e], ll[e]);
            ushort4 ph0 = {hh[0], hh[1], hh[2], hh[3]}, ph1 = {hh[4], hh[5], hh[6], hh[7]};
            ushort4 pl0 = {ll[0], ll[1], ll[2], ll[3]}, pl1 = {ll[4], ll[5], ll[6], ll[7]};
            uint16_t* d = sXh + row * 40 + q4 * 8;
            *(ushort4*)d = ph0; *(ushort4*)(d + 4) = ph1;
            d = sXl + row * 40 + q4 * 8;
            *(ushort4*)d = pl0; *(ushort4*)(d + 4) = pl1;
        }
        __syncthreads();

        #pragma unroll
        for (int s = 0; s < 2; ++s) {
            uint32_t ah[4], al[4];
            uint32_t offA = (uint32_t)((w * 16 + lrowA) * 80 + s * 32 + lcolA);
            ldsm4(ah, aEh + offA);
            ldsm4(al, aEl + offA);
            #pragma unroll
            for (int jj = 0; jj < 4; ++jj) {
                uint32_t offB = (uint32_t)((jj * 16 + bhalfB + browB) * 80 + s * 32 + bselB);
                uint32_t th[4], tl[4];
                ldsm4(th, aXh + offB);
                ldsm4(tl, aXl + offB);
                uint32_t bh0[2] = {th[0], th[1]}, bh1[2] = {th[2], th[3]};
                uint32_t bl0[2] = {tl[0], tl[1]}, bl1[2] = {tl[2], tl[3]};
                mma16816(acc[2*jj],   ah, bh0);
                mma16816(acc[2*jj],   ah, bl0);
                mma16816(acc[2*jj],   al, bh0);
                mma16816(acc[2*jj+1], ah, bh1);
                mma16816(acc[2*jj+1], ah, bl1);
                mma16816(acc[2*jj+1], al, bh1);
            }
        }
        __syncthreads();
    }

    int g = lane >> 2, q = lane & 3;
    int i0 = ibase + w * 16 + g;
    #pragma unroll
    for (int j8 = 0; j8 < 8; ++j8) {
        int t0 = j8 * 8 + q * 2;
        g_AGG[(size_t)t0 * (Bb * Nn) + b * Nn + i0]           = acc[j8][0];
        g_AGG[(size_t)(t0 + 1) * (Bb * Nn) + b * Nn + i0]     = acc[j8][1];
        g_AGG[(size_t)t0 * (Bb * Nn) + b * Nn + i0 + 8]       = acc[j8][2];
        g_AGG[(size_t)(t0 + 1) * (Bb * Nn) + b * Nn + i0 + 8] = acc[j8][3];
    }
}

// ---------------- K5p: persistent recurrence, W double-buffered uint4 loads ----------------
__device__ __forceinline__ void load_h(int kstep, int r, int kp, uint32_t* ah, uint32_t* al) {
    int k0 = kstep * 16;
    ah[0] = __ldcg((const uint32_t*)&g_hh[r * Nn + k0 + kp]);
    ah[1] = __ldcg((const uint32_t*)&g_hh[(r + 8) * Nn + k0 + kp]);
    ah[2] = __ldcg((const uint32_t*)&g_hh[r * Nn + k0 + 8 + kp]);
    ah[3] = __ldcg((const uint32_t*)&g_hh[(r + 8) * Nn + k0 + 8 + kp]);
    al[0] = __ldcg((const uint32_t*)&g_hl[r * Nn + k0 + kp]);
    al[1] = __ldcg((const uint32_t*)&g_hl[(r + 8) * Nn + k0 + kp]);
    al[2] = __ldcg((const uint32_t*)&g_hl[r * Nn + k0 + 8 + kp]);
    al[3] = __ldcg((const uint32_t*)&g_hl[(r + 8) * Nn + k0 + 8 + kp]);
}
__device__ __forceinline__ void load_w(int gate, int ntbase, int kstep, int lane, uint4* Wf) {
    #pragma unroll
    for (int j = 0; j < 4; ++j) {
        size_t idx = (((size_t)(gate * 256 + ntbase + j) * 128 + kstep) * 32 + lane);
        Wf[j] = __ldcg(&g_WF4[idx]);
    }
}

__global__ __launch_bounds__(256, 2) void k5p(
    const float* __restrict__ bhr, const float* __restrict__ bhz,
    const float* __restrict__ bhn)
{
    int tid = threadIdx.x;
    int bid = blockIdx.x;
    int nblkI = bid & 7;
    int ksI   = (bid >> 3) % KS3;
    int gate  = bid / (8 * KS3);
    int w = tid / 32, lane = tid % 32;
    int ntbase = nblkI * 32 + w * 4;
    int kb = (ksI * 128) / KS3;
    int ke = ((ksI + 1) * 128) / KS3;
    int r = lane >> 2;
    int kp = (lane & 3) * 2;

    int gid = bid * 256 + tid;
    float rb = 0.f, zb = 0.f, nb = 0.f, hloc = 0.f;
    bool own = (gid < Bb * Nn);
    if (own) { int i = gid % Nn; rb = bhr[i]; zb = bhz[i]; nb = bhn[i]; }

    float* Pme = g_part + (size_t)(gate * KS3 + ksI) * (Bb * Nn);
    unsigned target = 0;

    for (int t = 0; t < Ss; ++t) {
        float agg = own ? g_AGG[(size_t)t * (Bb * Nn) + gid] : 0.f;

        float acc[4][4];
        #pragma unroll
        for (int j = 0; j < 4; ++j)
            #pragma unroll
            for (int c = 0; c < 4; ++c) acc[j][c] = 0.f;

        uint32_t ah[4], al[4], ahn[4], aln[4];
        uint4 Wc[4], Wn[4];
        load_h(kb, r, kp, ah, al);
        load_w(gate, ntbase, kb, lane, Wc);
        #pragma unroll 2
        for (int kstep = kb; kstep < ke; ++kstep) {
            if (kstep + 1 < ke) {
                load_h(kstep + 1, r, kp, ahn, aln);
                load_w(gate, ntbase, kstep + 1, lane, Wn);
            }
            #pragma unroll
            for (int j = 0; j < 4; ++j) {
                uint32_t bh[2] = {Wc[j].x, Wc[j].y};
                uint32_t bl[2] = {Wc[j].z, Wc[j].w};
                mma16816(acc[j], ah, bh);
                mma16816(acc[j], ah, bl);
                mma16816(acc[j], al, bh);
            }
            #pragma unroll
            for (int u = 0; u < 4; ++u) { ah[u] = ahn[u]; al[u] = aln[u]; Wc[u] = Wn[u]; }
        }
        #pragma unroll
        for (int j = 0; j < 4; ++j) {
            int ncol = (ntbase + j) * 8 + kp;
            *(float2*)&Pme[r * Nn + ncol]       = make_float2(acc[j][0], acc[j][1]);
            *(float2*)&Pme[(r + 8) * Nn + ncol] = make_float2(acc[j][2], acc[j][3]);
        }

        target += NPB;
        __syncthreads();
        if (tid == 0) {
            __threadfence();
            atomicAdd(&g_barcnt, 1u);
            while (*(volatile unsigned*)&g_barcnt < target) __nanosleep(64);
        }
        __syncthreads();

        if (own) {
            float rl = rb, zl = zb, nl = nb;
            #pragma unroll
            for (int p = 0; p < KS3; ++p) {
                rl += __ldcg(&g_part[(size_t)(0 * KS3 + p) * (Bb * Nn) + gid]);
                zl += __ldcg(&g_part[(size_t)(1 * KS3 + p) * (Bb * Nn) + gid]);
                nl += __ldcg(&g_part[(size_t)(2 * KS3 + p) * (Bb * Nn) + gid]);
            }
            float rr = 1.f / (1.f + expf(-(agg + rl)));
            float zz = 1.f / (1.f + expf(-(agg + zl)));
            float nn2 = tanhf(agg + rr * nl);
            float hn = (1.f - zz) * nn2 + zz * hloc;
            hloc = hn;
            __nv_bfloat16 hb = __float2bfloat16(hn);
            g_hh[gid] = hb;
            g_hl[gid] = __float2bfloat16(hn - __bfloat162float(hb));
            if (t == Ss - 1) g_h[gid] = hn;
        }

        target += NPB;
        __syncthreads();
        if (tid == 0) {
            __threadfence();
            atomicAdd(&g_barcnt, 1u);
            while (*(volatile unsigned*)&g_barcnt < target) __nanosleep(64);
        }
        __syncthreads();
    }
}

// ---------------- K7: out[b] = h[b,:].Wo + bo ----------------
__global__ void k7_out(const float* __restrict__ Wo, const float* __restrict__ bo,
                       float* __restrict__ out)
{
    __shared__ float red[256];
    int b = blockIdx.x, tid = threadIdx.x;
    float s = 0.f;
    for (int i = tid; i < Nn; i += 256) s += g_h[b * Nn + i] * Wo[i];
    red[tid] = s;
    __syncthreads();
    for (int off = 128; off > 0; off >>= 1) {
        if (tid < off) red[tid] += red[tid + off];
        __syncthreads();
    }
    if (tid == 0) out[b] = red[0] + bo[0];
}

extern "C" void kernel_launch(void* const* d_in, const int* in_sizes, int n_in,
                              void* d_out, int out_size) {
    const float* x   = (const float*)d_in[0];
    const int*   adj = (const int*)  d_in[1];
    const float* Wq  = (const float*)d_in[2];
    const float* bq  = (const float*)d_in[3];
    const float* Wk  = (const float*)d_in[4];
    const float* bk  = (const float*)d_in[5];
    const float* Whr = (const float*)d_in[6];
    const float* bhr = (const float*)d_in[7];
    const float* Whz = (const float*)d_in[8];
    const float* bhz = (const float*)d_in[9];
    const float* Whn = (const float*)d_in[10];
    const float* bhn = (const float*)d_in[11];
    const float* Wo  = (const float*)d_in[12];
    const float* bo  = (const float*)d_in[13];
    float* out = (float*)d_out;

    kA<<<A_W, 256>>>(x, Wq, bq, Wk, bk, Whr, Whz, Whn);
    k2m<<<dim3(Nn / 128, Nn / 128, Bb), 256>>>(adj);
    k4m<<<dim3(Nn / 128, Bb), 256>>>(x);
    k5p<<<NPB, 256>>>(bhr, bhz, bhn);
    k7_out<<<Bb, 256>>>(Wo, bo, out);
}